// round 13
// baseline (speedup 1.0000x reference)
#include <cuda_runtime.h>
#include <cuda_bf16.h>
#include <cuda_fp16.h>
#include <cstdint>

#define N_NODES 8192
#define IN_F    128
#define HID     64
#define OUT_F   128
#define BM      64
#define BN      64

// persistent schedule: 16384 units = 128 mtiles x 128 jblocks, 296 CTAs
// start(c) = 55c + min(c,104)  (CTAs 0..103 have 56 units, rest 55)
#define N_CTAS  296
#define UNIT_Q  55
#define UNIT_R  104
#define CF_THRESH 5824   // start(104)
#define SLOTS   4

// K/V row stride in flash smem: 64 elems + 8 pad = 72 x 2B = 36 words = 9 uint4.
#define KSTRW 36
#define KSTR4 9
// uint4 per buffer: Kh 576, Kl 576, V 1152 -> 2304 u4 = 36864 B ; 3 buffers
#define BUF_U4 2304
#define FLASH_SMEM (3 * BUF_U4 * 16)   // 110592 B -> 2 CTAs/SM

// gemm_prep smem B row stride: 128 bf16 = 64 words data + 4 pad = 68 words = 17 u4
#define PSTRW 68
#define PSTR4 17
#define PREP_SMEM (2 * 128 * PSTRW * 4)   // Bh + Bl = 69632 B

// ---------------- scratch (static device globals; no allocs allowed) -----
__device__ __align__(16) __nv_bfloat16 g_hh[N_NODES * IN_F];   // h hi
__device__ __align__(16) __nv_bfloat16 g_hl[N_NODES * IN_F];   // h lo
__device__ __align__(16) __nv_bfloat16 g_Wth[256 * IN_F];      // Wcat^T hi [col][k]
__device__ __align__(16) __nv_bfloat16 g_Wtl[256 * IN_F];      // Wcat^T lo
__device__ __align__(16) __nv_bfloat16 g_Qh[N_NODES * HID];
__device__ __align__(16) __nv_bfloat16 g_Ql[N_NODES * HID];
__device__ __align__(16) __nv_bfloat16 g_Kh[N_NODES * HID];
__device__ __align__(16) __nv_bfloat16 g_Kl[N_NODES * HID];
__device__ __align__(16) __half g_Vt[OUT_F * N_NODES];         // V^T fp16 [feat][j]
// partial slots per m-tile + completion counters
__device__ __align__(16) float g_Op[SLOTS][N_NODES][OUT_F];
__device__ float g_pm[SLOTS][N_NODES];
__device__ float g_pl[SLOTS][N_NODES];
__device__ int   g_cnt[128];

// ---------------- helpers --------------------------------------------------
__device__ __forceinline__ void cp16(void* s, const void* g) {
    unsigned sa = (unsigned)__cvta_generic_to_shared(s);
    asm volatile("cp.async.cg.shared.global [%0], [%1], 16;\n" :: "r"(sa), "l"(g));
}
__device__ __forceinline__ void cp_commit() { asm volatile("cp.async.commit_group;\n"); }
template <int N> __device__ __forceinline__ void cp_wait() {
    asm volatile("cp.async.wait_group %0;\n" :: "n"(N));
}
__device__ __forceinline__ void mma_bf16(float c[4],
                                         unsigned a0, unsigned a1, unsigned a2, unsigned a3,
                                         unsigned b0, unsigned b1) {
    asm volatile(
        "mma.sync.aligned.m16n8k16.row.col.f32.bf16.bf16.f32 "
        "{%0,%1,%2,%3}, {%4,%5,%6,%7}, {%8,%9}, {%0,%1,%2,%3};\n"
        : "+f"(c[0]), "+f"(c[1]), "+f"(c[2]), "+f"(c[3])
        : "r"(a0), "r"(a1), "r"(a2), "r"(a3), "r"(b0), "r"(b1));
}
__device__ __forceinline__ void mma_f16(float c[4],
                                        unsigned a0, unsigned a1, unsigned a2, unsigned a3,
                                        unsigned b0, unsigned b1) {
    asm volatile(
        "mma.sync.aligned.m16n8k16.row.col.f32.f16.f16.f32 "
        "{%0,%1,%2,%3}, {%4,%5,%6,%7}, {%8,%9}, {%0,%1,%2,%3};\n"
        : "+f"(c[0]), "+f"(c[1]), "+f"(c[2]), "+f"(c[3])
        : "r"(a0), "r"(a1), "r"(a2), "r"(a3), "r"(b0), "r"(b1));
}
__device__ __forceinline__ unsigned pack_bf2(__nv_bfloat16 a, __nv_bfloat16 b) {
    return (unsigned)__bfloat16_as_ushort(a) |
           ((unsigned)__bfloat16_as_ushort(b) << 16);
}
__device__ __forceinline__ unsigned pack_h2(__half a, __half b) {
    return (unsigned)__half_as_ushort(a) |
           ((unsigned)__half_as_ushort(b) << 16);
}
__device__ __forceinline__ void split_bf(float v, __nv_bfloat16& hi, __nv_bfloat16& lo) {
    hi = __float2bfloat16(v);
    lo = __float2bfloat16(v - __bfloat162float(hi));
}
__device__ __forceinline__ int cfirst_of(int ut) {
    return (ut < CF_THRESH) ? (ut / 56) : ((ut - UNIT_R) / UNIT_Q);
}

// ---------------- split: h and Wcat^T -> bf16 hi/lo + counter reset --------
// blocks 0..511: h, 2 float4 per thread (MLP 2). blocks 512..543: W.
__global__ __launch_bounds__(256)
void split_kernel(const float* __restrict__ h,
                  const float* __restrict__ Ws,
                  const float* __restrict__ Wt,
                  const float* __restrict__ Wc) {
    const int bid = blockIdx.x;
    if (bid < 512) {
        int i0 = (bid * 256 + threadIdx.x) * 8;   // 8 floats = 2 float4
        float4 va = *(const float4*)(h + i0);
        float4 vb = *(const float4*)(h + i0 + 4);
        union { __nv_bfloat16 b[4]; uint2 u; } pha, pla, phb, plb;
        split_bf(va.x, pha.b[0], pla.b[0]);
        split_bf(va.y, pha.b[1], pla.b[1]);
        split_bf(va.z, pha.b[2], pla.b[2]);
        split_bf(va.w, pha.b[3], pla.b[3]);
        split_bf(vb.x, phb.b[0], plb.b[0]);
        split_bf(vb.y, phb.b[1], plb.b[1]);
        split_bf(vb.z, phb.b[2], plb.b[2]);
        split_bf(vb.w, phb.b[3], plb.b[3]);
        *(uint2*)(g_hh + i0)     = pha.u;
        *(uint2*)(g_hh + i0 + 4) = phb.u;
        *(uint2*)(g_hl + i0)     = pla.u;
        *(uint2*)(g_hl + i0 + 4) = plb.u;
    } else {
        if (bid == 512 && threadIdx.x < 128) g_cnt[threadIdx.x] = 0;
        int t = (bid - 512) * 256 + threadIdx.x;    // 0..8191
        int c  = t >> 5;                            // concat col 0..255
        int k0 = (t & 31) * 4;
        const float* W; int stride, cc;
        if (c < 64)       { W = Ws; stride = 64;  cc = c; }
        else if (c < 128) { W = Wt; stride = 64;  cc = c - 64; }
        else              { W = Wc; stride = 128; cc = c - 128; }
        union { __nv_bfloat16 b[4]; uint2 u; } ph, pl;
#pragma unroll
        for (int j = 0; j < 4; j++)
            split_bf(W[(k0 + j) * stride + cc], ph.b[j], pl.b[j]);
        *(uint2*)(g_Wth + c * IN_F + k0) = ph.u;
        *(uint2*)(g_Wtl + c * IN_F + k0) = pl.u;
    }
}

// ---------------- gemm_prep: C = h @ Wcat (3-term bf16) --------------------
__global__ __launch_bounds__(128, 2)
void gemm_prep() {
    extern __shared__ __align__(16) unsigned char psmem[];
    unsigned* sBh = (unsigned*)psmem;                    // [128][68 words]
    unsigned* sBl = sBh + 128 * PSTRW;

    const int tid  = threadIdx.x;
    const int warp = tid >> 5;
    const int lane = tid & 31;
    const int lr   = lane >> 2;
    const int qi   = lane & 3;

    const int mtile = blockIdx.x & 127;
    const int ntile = blockIdx.x >> 7;
    const int row0  = mtile * 64 + warp * 16 + lr;
    const int row1  = row0 + 8;

    {
        const uint4* gWh4 = (const uint4*)g_Wth;
        const uint4* gWl4 = (const uint4*)g_Wtl;
        uint4* sBh4 = (uint4*)sBh;
        uint4* sBl4 = (uint4*)sBl;
#pragma unroll
        for (int i = tid; i < 2048; i += 128) {
            int r = i >> 4, u = i & 15;
            cp16(&sBh4[r * PSTR4 + u], &gWh4[(ntile * 128 + r) * 16 + u]);
            cp16(&sBl4[r * PSTR4 + u], &gWl4[(ntile * 128 + r) * 16 + u]);
        }
        cp_commit();
    }

    const unsigned* hh32 = (const unsigned*)g_hh;
    const unsigned* hl32 = (const unsigned*)g_hl;
    unsigned ah[8][4], al[8][4];
#pragma unroll
    for (int kt = 0; kt < 8; kt++) {
        int b0 = row0 * 64 + qi + 8 * kt;
        int b1 = row1 * 64 + qi + 8 * kt;
        ah[kt][0] = hh32[b0];     ah[kt][1] = hh32[b1];
        ah[kt][2] = hh32[b0 + 4]; ah[kt][3] = hh32[b1 + 4];
        al[kt][0] = hl32[b0];     al[kt][1] = hl32[b1];
        al[kt][2] = hl32[b0 + 4]; al[kt][3] = hl32[b1 + 4];
    }

    float C[16][4];
#pragma unroll
    for (int nt = 0; nt < 16; nt++)
        C[nt][0] = C[nt][1] = C[nt][2] = C[nt][3] = 0.f;

    cp_wait<0>();
    __syncthreads();

#pragma unroll
    for (int kt = 0; kt < 8; kt++) {
#pragma unroll
        for (int g2 = 0; g2 < 4; g2++) {
            unsigned b0[4], b1[4], c0[4], c1[4];
#pragma unroll
            for (int i = 0; i < 4; i++) {
                int nt = 4 * g2 + i;
                int bi = (8 * nt + lr) * PSTRW + qi + 8 * kt;
                b0[i] = sBh[bi]; b1[i] = sBh[bi + 4];
                c0[i] = sBl[bi]; c1[i] = sBl[bi + 4];
            }
#pragma unroll
            for (int i = 0; i < 4; i++)
                mma_bf16(C[4*g2+i], ah[kt][0], ah[kt][1], ah[kt][2], ah[kt][3], b0[i], b1[i]);
#pragma unroll
            for (int i = 0; i < 4; i++)
                mma_bf16(C[4*g2+i], al[kt][0], al[kt][1], al[kt][2], al[kt][3], b0[i], b1[i]);
#pragma unroll
            for (int i = 0; i < 4; i++)
                mma_bf16(C[4*g2+i], ah[kt][0], ah[kt][1], ah[kt][2], ah[kt][3], c0[i], c1[i]);
        }
    }

    if (ntile == 0) {
#pragma unroll
        for (int nt = 0; nt < 16; nt++) {
            __nv_bfloat16 h0, l0, h1, l1, h2, l2, h3, l3;
            split_bf(C[nt][0], h0, l0); split_bf(C[nt][1], h1, l1);
            split_bf(C[nt][2], h2, l2); split_bf(C[nt][3], h3, l3);
            int col = 8 * nt + 2 * qi;
            __nv_bfloat16* dh = (col < 64) ? g_Qh : g_Kh;
            __nv_bfloat16* dl = (col < 64) ? g_Ql : g_Kl;
            int c = col & 63;
            *(unsigned*)&dh[(size_t)row0 * HID + c] = pack_bf2(h0, h1);
            *(unsigned*)&dl[(size_t)row0 * HID + c] = pack_bf2(l0, l1);
            *(unsigned*)&dh[(size_t)row1 * HID + c] = pack_bf2(h2, h3);
            *(unsigned*)&dl[(size_t)row1 * HID + c] = pack_bf2(l2, l3);
        }
    } else {
#pragma unroll
        for (int nt = 0; nt < 16; nt++) {
            int col = 8 * nt + 2 * qi;
            g_Vt[(size_t)col       * N_NODES + row0] = __float2half_rn(C[nt][0]);
            g_Vt[(size_t)(col + 1) * N_NODES + row0] = __float2half_rn(C[nt][1]);
            g_Vt[(size_t)col       * N_NODES + row1] = __float2half_rn(C[nt][2]);
            g_Vt[(size_t)(col + 1) * N_NODES + row1] = __float2half_rn(C[nt][3]);
        }
    }
}

// ---------------- flash attention (persistent, occ 2, fused merge) ---------
// grid = 296 CTAs; CTA c owns flattened units [start(c), start(c+1)).
__global__ __launch_bounds__(128, 2)
void flash_kernel(const int* __restrict__ adj, float* __restrict__ out) {
    extern __shared__ __align__(16) unsigned char dynsmem[];
    uint4* base4 = (uint4*)dynsmem;
    __shared__ int s_flag;

    const int tid  = threadIdx.x;
    const int warp = tid >> 5;
    const int lane = tid & 31;
    const int lr   = lane >> 2;
    const int qi   = lane & 3;

    const int c  = blockIdx.x;
    const int u0 = UNIT_Q * c + min(c, UNIT_R);
    const int u1 = u0 + UNIT_Q + (c < UNIT_R ? 1 : 0);

    const int2*  adj2 = (const int2*)adj;
    const uint4* gKh4 = (const uint4*)g_Kh;
    const uint4* gKl4 = (const uint4*)g_Kl;
    const uint4* gV4  = (const uint4*)g_Vt;
    const unsigned* qh32 = (const unsigned*)g_Qh;
    const unsigned* ql32 = (const unsigned*)g_Ql;

    int u = u0;
    while (u < u1) {
        const int t    = u >> 7;           // m-tile
        const int jb0  = u & 127;          // first j-block in this tile
        const int nit  = min(128 - jb0, u1 - u);
        const int cf   = cfirst_of(t << 7);
        const int slot = c - cf;
        const int jbase = jb0 * BN;

        const int mr   = t * BM + warp * 16;
        const int row0 = mr + lr;
        const int row1 = row0 + 8;

        // Q fragments (hi/lo)
        unsigned qh[4][4], ql[4][4];
#pragma unroll
        for (int kt = 0; kt < 4; kt++) {
            int b0 = row0 * 32 + qi + 8 * kt;
            int b1 = row1 * 32 + qi + 8 * kt;
            qh[kt][0] = qh32[b0];     qh[kt][1] = qh32[b1];
            qh[kt][2] = qh32[b0 + 4]; qh[kt][3] = qh32[b1 + 4];
            ql[kt][0] = ql32[b0];     ql[kt][1] = ql32[b1];
            ql[kt][2] = ql32[b0 + 4]; ql[kt][3] = ql32[b1 + 4];
        }

        float O[16][4];
#pragma unroll
        for (int v = 0; v < 16; v++)
#pragma unroll
            for (int i = 0; i < 4; i++) O[v][i] = 0.f;
        float m0 = -1e30f, m1 = -1e30f, l0 = 0.f, l1 = 0.f;

        // segment prologue: prior segment done before refill
        __syncthreads();
        {
            uint4* bKh = base4;
            uint4* bKl = base4 + 576;
            uint4* bV  = base4 + 1152;
#pragma unroll
            for (int i = tid; i < 512; i += 128) {
                int r = i >> 3, cw = i & 7;
                cp16(&bKh[r * KSTR4 + cw], &gKh4[(jbase + r) * 8 + cw]);
                cp16(&bKl[r * KSTR4 + cw], &gKl4[(jbase + r) * 8 + cw]);
            }
#pragma unroll
            for (int i = tid; i < 1024; i += 128) {
                int cl2 = i >> 3, kw = i & 7;
                cp16(&bV[cl2 * KSTR4 + kw], &gV4[cl2 * 1024 + (jbase >> 3) + kw]);
            }
            cp_commit();
        }

        int b_cur = 0;
        for (int it = 0; it < nit; ++it) {
            const int j0 = jbase + it * BN;

            int2 adjA[8], adjB[8];
#pragma unroll
            for (int nt = 0; nt < 8; nt++) {
                adjA[nt] = __ldcs(&adj2[row0 * 4096 + (j0 >> 1) + 4 * nt + qi]);
                adjB[nt] = __ldcs(&adj2[row1 * 4096 + (j0 >> 1) + 4 * nt + qi]);
            }

            cp_wait<0>();
            __syncthreads();   // single barrier per iter (3-buffer reuse distance 2)

            if (it + 1 < nit) {
                const int jn = j0 + BN;
                const int b_nxt = (b_cur == 2) ? 0 : b_cur + 1;
                uint4* bKh = base4 + b_nxt * BUF_U4;
                uint4* bKl = bKh + 576;
                uint4* bV  = bKh + 1152;
#pragma unroll
                for (int i = tid; i < 512; i += 128) {
                    int r = i >> 3, cw = i & 7;
                    cp16(&bKh[r * KSTR4 + cw], &gKh4[(jn + r) * 8 + cw]);
                    cp16(&bKl[r * KSTR4 + cw], &gKl4[(jn + r) * 8 + cw]);
                }
#pragma unroll
                for (int i = tid; i < 1024; i += 128) {
                    int cl2 = i >> 3, kw = i & 7;
                    cp16(&bV[cl2 * KSTR4 + kw], &gV4[cl2 * 1024 + (jn >> 3) + kw]);
                }
                cp_commit();
            }

            const unsigned* sKh32 = (const unsigned*)(base4 + b_cur * BUF_U4);
            const unsigned* sKl32 = sKh32 + 576 * 4;
            const unsigned* sV32  = sKh32 + 1152 * 4;

            // S = Q K^T (3-term bf16 split, chains interleaved x4)
            float S[8][4];
#pragma unroll
            for (int nt = 0; nt < 8; nt++)
                S[nt][0] = S[nt][1] = S[nt][2] = S[nt][3] = 0.f;

#pragma unroll
            for (int kt = 0; kt < 4; kt++) {
#pragma unroll
                for (int gr = 0; gr < 2; gr++) {
                    unsigned b0[4], b1[4], c0[4], c1[4];
#pragma unroll
                    for (int i = 0; i < 4; i++) {
                        int nt = 4 * gr + i;
                        int bi = (8 * nt + lr) * KSTRW + qi + 8 * kt;
                        b0[i] = sKh32[bi]; b1[i] = sKh32[bi + 4];
                        c0[i] = sKl32[bi]; c1[i] = sKl32[bi + 4];
                    }
#pragma unroll
                    for (int i = 0; i < 4; i++)
                        mma_bf16(S[4*gr+i], qh[kt][0], qh[kt][1], qh[kt][2], qh[kt][3], b0[i], b1[i]);
#pragma unroll
                    for (int i = 0; i < 4; i++)
                        mma_bf16(S[4*gr+i], ql[kt][0], ql[kt][1], ql[kt][2], ql[kt][3], b0[i], b1[i]);
#pragma unroll
                    for (int i = 0; i < 4; i++)
                        mma_bf16(S[4*gr+i], qh[kt][0], qh[kt][1], qh[kt][2], qh[kt][3], c0[i], c1[i]);
                }
            }

            // mask + row max
            float rmax0 = -1e30f, rmax1 = -1e30f;
#pragma unroll
            for (int nt = 0; nt < 8; nt++) {
                if (adjA[nt].x <= 0) S[nt][0] = -1e30f;
                if (adjA[nt].y <= 0) S[nt][1] = -1e30f;
                if (adjB[nt].x <= 0) S[nt][2] = -1e30f;
                if (adjB[nt].y <= 0) S[nt][3] = -1e30f;
                rmax0 = fmaxf(rmax0, fmaxf(S[nt][0], S[nt][1]));
                rmax1 = fmaxf(rmax1, fmaxf(S[nt][2], S[nt][3]));
            }
            rmax0 = fmaxf(rmax0, __shfl_xor_sync(0xffffffffu, rmax0, 1));
            rmax0 = fmaxf(rmax0, __shfl_xor_sync(0xffffffffu, rmax0, 2));
            rmax1 = fmaxf(rmax1, __shfl_xor_sync(0xffffffffu, rmax1, 1));
            rmax1 = fmaxf(rmax1, __shfl_xor_sync(0xffffffffu, rmax1, 2));

            float mn0 = fmaxf(m0, rmax0), mn1 = fmaxf(m1, rmax1);
            float sc0 = __expf(m0 - mn0), sc1 = __expf(m1 - mn1);
            m0 = mn0; m1 = mn1;

            // exp + pack P (fp16)
            float rs0 = 0.f, rs1 = 0.f;
            unsigned ap[4][4];
#pragma unroll
            for (int kt2 = 0; kt2 < 4; kt2++) {
#pragma unroll
                for (int half = 0; half < 2; half++) {
                    int nt = 2 * kt2 + half;
                    float p0 = (S[nt][0] > -1e29f) ? __expf(S[nt][0] - mn0) : 0.f;
                    float p1 = (S[nt][1] > -1e29f) ? __expf(S[nt][1] - mn0) : 0.f;
                    float p2 = (S[nt][2] > -1e29f) ? __expf(S[nt][2] - mn1) : 0.f;
                    float p3 = (S[nt][3] > -1e29f) ? __expf(S[nt][3] - mn1) : 0.f;
                    rs0 += p0 + p1;
                    rs1 += p2 + p3;
                    ap[kt2][2 * half + 0] = pack_h2(__float2half_rn(p0), __float2half_rn(p1));
                    ap[kt2][2 * half + 1] = pack_h2(__float2half_rn(p2), __float2half_rn(p3));
                }
            }

            rs0 += __shfl_xor_sync(0xffffffffu, rs0, 1);
            rs0 += __shfl_xor_sync(0xffffffffu, rs0, 2);
            rs1 += __shfl_xor_sync(0xffffffffu, rs1, 1);
            rs1 += __shfl_xor_sync(0xffffffffu, rs1, 2);
            l0 = l0 * sc0 + rs0;
            l1 = l1 * sc1 + rs1;

            if (!__all_sync(0xffffffffu, (sc0 == 1.f) & (sc1 == 1.f))) {
#pragma unroll
                for (int v = 0; v < 16; v++) {
                    O[v][0] *= sc0; O[v][1] *= sc0;
                    O[v][2] *= sc1; O[v][3] *= sc1;
                }
            }

            // O += P V (single fp16 term, chains interleaved x4)
#pragma unroll
            for (int kt2 = 0; kt2 < 4; kt2++) {
#pragma unroll
                for (int gr = 0; gr < 4; gr++) {
                    unsigned v0[4], v1[4];
#pragma unroll
                    for (int i = 0; i < 4; i++) {
                        int vn = 4 * gr + i;
                        int bi = (8 * vn + lr) * KSTRW + qi + 8 * kt2;
                        v0[i] = sV32[bi]; v1[i] = sV32[bi + 4];
                    }
#pragma unroll
                    for (int i = 0; i < 4; i++)
                        mma_f16(O[4*gr+i], ap[kt2][0], ap[kt2][1], ap[kt2][2], ap[kt2][3], v0[i], v1[i]);
                }
            }

            b_cur = (b_cur == 2) ? 0 : b_cur + 1;
        }

        // write this segment's partials (unnormalized)
        float* op = &g_Op[slot][0][0];
#pragma unroll
        for (int vn = 0; vn < 16; vn++) {
            int col = 8 * vn + 2 * qi;
            *(float2*)&op[row0 * OUT_F + col] = make_float2(O[vn][0], O[vn][1]);
            *(float2*)&op[row1 * OUT_F + col] = make_float2(O[vn][2], O[vn][3]);
        }
        if (qi == 0) {
            g_pm[slot][row0] = m0; g_pl[slot][row0] = l0;
            g_pm[slot][row1] = m1; g_pl[slot][row1] = l1;
        }

        // ---- fused merge: last CTA of this tile normalizes + writes out --
        const int ns = cfirst_of((t << 7) + 127) - cf + 1;
        __threadfence();                 // release this CTA's partials
        __syncthreads();
        if (tid == 0) {
            int old = atomicAdd(&g_cnt[t], 1);
            s_flag = (old == ns - 1);
        }
        __syncthreads();
        if (s_flag) {
            __threadfence();             // acquire other CTAs' partials
            const int rbase = t * BM;
            for (int i = tid; i < BM * 32; i += 128) {
                int row = rbase + (i >> 5);
                int cc  = (i & 31) * 4;
                float M = g_pm[0][row];
                float L = g_pl[0][row];
                float4 acc = *(const float4*)&g_Op[0][row][cc];
                for (int s = 1; s < ns; s++) {
                    float m = g_pm[s][row], l = g_pl[s][row];
                    float Mn = fmaxf(M, m);
                    float sa = __expf(M - Mn), sb = __expf(m - Mn);
                    float4 b = *(const float4*)&g_Op[s][row][cc];
                    acc.x = acc.x * sa + b.x * sb;
                    acc.y = acc.y * sa + b.y * sb;
                    acc.z = acc.z * sa + b.z * sb;
                    acc.w = acc.w * sa + b.w * sb;
                    L = L * sa + l * sb;
                    M = Mn;
                }
                float inv = 1.f / L;
                *(float4*)&out[row * OUT_F + cc] =
                    make_float4(acc.x * inv, acc.y * inv, acc.z * inv, acc.w * inv);
            }
        }

        u += nit;
    }
}

// ---------------- launch --------------------------------------------------
extern "C" void kernel_launch(void* const* d_in, const int* in_sizes, int n_in,
                              void* d_out, int out_size) {
    const float* h   = (const float*)d_in[0];
    const int*   adj = (const int*)d_in[1];
    const float* Ws  = (const float*)d_in[2];
    const float* Wt  = (const float*)d_in[3];
    const float* Wc  = (const float*)d_in[4];
    float* out = (float*)d_out;

    split_kernel<<<544, 256>>>(h, Ws, Wt, Wc);

    cudaFuncSetAttribute(gemm_prep,
                         cudaFuncAttributeMaxDynamicSharedMemorySize, PREP_SMEM);
    gemm_prep<<<256, 128, PREP_SMEM>>>();

    cudaFuncSetAttribute(flash_kernel,
                         cudaFuncAttributeMaxDynamicSharedMemorySize, FLASH_SMEM);
    flash_kernel<<<N_CTAS, 128, FLASH_SMEM>>>(adj, out);
}

// round 14
// speedup vs baseline: 1.0077x; 1.0077x over previous
#include <cuda_runtime.h>
#include <cuda_bf16.h>
#include <cuda_fp16.h>
#include <cstdint>

#define N_NODES 8192
#define IN_F    128
#define HID     64
#define OUT_F   128
#define BM      64
#define BN      64

// persistent schedule: 16384 units = 128 mtiles x 128 jblocks, 296 CTAs
// start(c) = 55c + min(c,104)  (CTAs 0..103 have 56 units, rest 55)
#define N_CTAS  296
#define UNIT_Q  55
#define UNIT_R  104
#define CF_THRESH 5824   // start(104)
#define SLOTS   4

// K/V row stride in flash smem: 64 elems + 8 pad = 72 x 2B = 36 words = 9 uint4.
#define KSTRW 36
#define KSTR4 9
// uint4 per buffer: Kh 576, Kl 576, V 1152 -> 2304 u4 = 36864 B ; 3 buffers
#define BUF_U4 2304
#define FLASH_SMEM (3 * BUF_U4 * 16)   // 110592 B -> 2 CTAs/SM

// gemm_prep smem B row stride: 128 bf16 = 64 words data + 4 pad = 68 words = 17 u4
#define PSTRW 68
#define PSTR4 17
#define PREP_SMEM (2 * 128 * PSTRW * 4)   // Bh + Bl = 69632 B

// ---------------- scratch (static device globals; no allocs allowed) -----
__device__ __align__(16) __nv_bfloat16 g_hh[N_NODES * IN_F];   // h hi
__device__ __align__(16) __nv_bfloat16 g_hl[N_NODES * IN_F];   // h lo
__device__ __align__(16) __nv_bfloat16 g_Wth[256 * IN_F];      // Wcat^T hi [col][k]
__device__ __align__(16) __nv_bfloat16 g_Wtl[256 * IN_F];      // Wcat^T lo
__device__ __align__(16) __nv_bfloat16 g_Qh[N_NODES * HID];
__device__ __align__(16) __nv_bfloat16 g_Ql[N_NODES * HID];
__device__ __align__(16) __nv_bfloat16 g_Kh[N_NODES * HID];
__device__ __align__(16) __nv_bfloat16 g_Kl[N_NODES * HID];
__device__ __align__(16) __half g_Vt[OUT_F * N_NODES];         // V^T fp16 [feat][j]
// partial slots per m-tile: normalized O in fp16 + (m, l) in fp32
__device__ __align__(16) __half g_Oph[SLOTS][N_NODES][OUT_F];
__device__ float g_pm[SLOTS][N_NODES];
__device__ float g_pl[SLOTS][N_NODES];

// ---------------- helpers --------------------------------------------------
__device__ __forceinline__ void cp16(void* s, const void* g) {
    unsigned sa = (unsigned)__cvta_generic_to_shared(s);
    asm volatile("cp.async.cg.shared.global [%0], [%1], 16;\n" :: "r"(sa), "l"(g));
}
__device__ __forceinline__ void cp_commit() { asm volatile("cp.async.commit_group;\n"); }
template <int N> __device__ __forceinline__ void cp_wait() {
    asm volatile("cp.async.wait_group %0;\n" :: "n"(N));
}
__device__ __forceinline__ void mma_bf16(float c[4],
                                         unsigned a0, unsigned a1, unsigned a2, unsigned a3,
                                         unsigned b0, unsigned b1) {
    asm volatile(
        "mma.sync.aligned.m16n8k16.row.col.f32.bf16.bf16.f32 "
        "{%0,%1,%2,%3}, {%4,%5,%6,%7}, {%8,%9}, {%0,%1,%2,%3};\n"
        : "+f"(c[0]), "+f"(c[1]), "+f"(c[2]), "+f"(c[3])
        : "r"(a0), "r"(a1), "r"(a2), "r"(a3), "r"(b0), "r"(b1));
}
__device__ __forceinline__ void mma_f16(float c[4],
                                        unsigned a0, unsigned a1, unsigned a2, unsigned a3,
                                        unsigned b0, unsigned b1) {
    asm volatile(
        "mma.sync.aligned.m16n8k16.row.col.f32.f16.f16.f32 "
        "{%0,%1,%2,%3}, {%4,%5,%6,%7}, {%8,%9}, {%0,%1,%2,%3};\n"
        : "+f"(c[0]), "+f"(c[1]), "+f"(c[2]), "+f"(c[3])
        : "r"(a0), "r"(a1), "r"(a2), "r"(a3), "r"(b0), "r"(b1));
}
__device__ __forceinline__ unsigned pack_bf2(__nv_bfloat16 a, __nv_bfloat16 b) {
    return (unsigned)__bfloat16_as_ushort(a) |
           ((unsigned)__bfloat16_as_ushort(b) << 16);
}
__device__ __forceinline__ unsigned pack_h2(__half a, __half b) {
    return (unsigned)__half_as_ushort(a) |
           ((unsigned)__half_as_ushort(b) << 16);
}
__device__ __forceinline__ void split_bf(float v, __nv_bfloat16& hi, __nv_bfloat16& lo) {
    hi = __float2bfloat16(v);
    lo = __float2bfloat16(v - __bfloat162float(hi));
}
__device__ __forceinline__ int cfirst_of(int ut) {
    return (ut < CF_THRESH) ? (ut / 56) : ((ut - UNIT_R) / UNIT_Q);
}

// S = Q K^T (3-term bf16 split, chains interleaved x4) into Sd
__device__ __forceinline__ void compute_S(float (&Sd)[8][4],
                                          const unsigned* sKh32, const unsigned* sKl32,
                                          const unsigned (&qh)[4][4], const unsigned (&ql)[4][4],
                                          int lr, int qi) {
#pragma unroll
    for (int nt = 0; nt < 8; nt++)
        Sd[nt][0] = Sd[nt][1] = Sd[nt][2] = Sd[nt][3] = 0.f;
#pragma unroll
    for (int kt = 0; kt < 4; kt++) {
#pragma unroll
        for (int gr = 0; gr < 2; gr++) {
            unsigned b0[4], b1[4], c0[4], c1[4];
#pragma unroll
            for (int i = 0; i < 4; i++) {
                int nt = 4 * gr + i;
                int bi = (8 * nt + lr) * KSTRW + qi + 8 * kt;
                b0[i] = sKh32[bi]; b1[i] = sKh32[bi + 4];
                c0[i] = sKl32[bi]; c1[i] = sKl32[bi + 4];
            }
#pragma unroll
            for (int i = 0; i < 4; i++)
                mma_bf16(Sd[4*gr+i], qh[kt][0], qh[kt][1], qh[kt][2], qh[kt][3], b0[i], b1[i]);
#pragma unroll
            for (int i = 0; i < 4; i++)
                mma_bf16(Sd[4*gr+i], ql[kt][0], ql[kt][1], ql[kt][2], ql[kt][3], b0[i], b1[i]);
#pragma unroll
            for (int i = 0; i < 4; i++)
                mma_bf16(Sd[4*gr+i], qh[kt][0], qh[kt][1], qh[kt][2], qh[kt][3], c0[i], c1[i]);
        }
    }
}

// ---------------- split: h and Wcat^T -> bf16 hi/lo ------------------------
__global__ __launch_bounds__(256)
void split_kernel(const float* __restrict__ h,
                  const float* __restrict__ Ws,
                  const float* __restrict__ Wt,
                  const float* __restrict__ Wc) {
    const int bid = blockIdx.x;
    if (bid < 512) {
        int i0 = (bid * 256 + threadIdx.x) * 8;
        float4 va = *(const float4*)(h + i0);
        float4 vb = *(const float4*)(h + i0 + 4);
        union { __nv_bfloat16 b[4]; uint2 u; } pha, pla, phb, plb;
        split_bf(va.x, pha.b[0], pla.b[0]);
        split_bf(va.y, pha.b[1], pla.b[1]);
        split_bf(va.z, pha.b[2], pla.b[2]);
        split_bf(va.w, pha.b[3], pla.b[3]);
        split_bf(vb.x, phb.b[0], plb.b[0]);
        split_bf(vb.y, phb.b[1], plb.b[1]);
        split_bf(vb.z, phb.b[2], plb.b[2]);
        split_bf(vb.w, phb.b[3], plb.b[3]);
        *(uint2*)(g_hh + i0)     = pha.u;
        *(uint2*)(g_hh + i0 + 4) = phb.u;
        *(uint2*)(g_hl + i0)     = pla.u;
        *(uint2*)(g_hl + i0 + 4) = plb.u;
    } else {
        int t = (bid - 512) * 256 + threadIdx.x;    // 0..8191
        int c  = t >> 5;
        int k0 = (t & 31) * 4;
        const float* W; int stride, cc;
        if (c < 64)       { W = Ws; stride = 64;  cc = c; }
        else if (c < 128) { W = Wt; stride = 64;  cc = c - 64; }
        else              { W = Wc; stride = 128; cc = c - 128; }
        union { __nv_bfloat16 b[4]; uint2 u; } ph, pl;
#pragma unroll
        for (int j = 0; j < 4; j++)
            split_bf(W[(k0 + j) * stride + cc], ph.b[j], pl.b[j]);
        *(uint2*)(g_Wth + c * IN_F + k0) = ph.u;
        *(uint2*)(g_Wtl + c * IN_F + k0) = pl.u;
    }
}

// ---------------- gemm_prep: C = h @ Wcat (3-term bf16) --------------------
__global__ __launch_bounds__(128, 2)
void gemm_prep() {
    extern __shared__ __align__(16) unsigned char psmem[];
    unsigned* sBh = (unsigned*)psmem;                    // [128][68 words]
    unsigned* sBl = sBh + 128 * PSTRW;

    const int tid  = threadIdx.x;
    const int warp = tid >> 5;
    const int lane = tid & 31;
    const int lr   = lane >> 2;
    const int qi   = lane & 3;

    const int mtile = blockIdx.x & 127;
    const int ntile = blockIdx.x >> 7;
    const int row0  = mtile * 64 + warp * 16 + lr;
    const int row1  = row0 + 8;

    {
        const uint4* gWh4 = (const uint4*)g_Wth;
        const uint4* gWl4 = (const uint4*)g_Wtl;
        uint4* sBh4 = (uint4*)sBh;
        uint4* sBl4 = (uint4*)sBl;
#pragma unroll
        for (int i = tid; i < 2048; i += 128) {
            int r = i >> 4, u = i & 15;
            cp16(&sBh4[r * PSTR4 + u], &gWh4[(ntile * 128 + r) * 16 + u]);
            cp16(&sBl4[r * PSTR4 + u], &gWl4[(ntile * 128 + r) * 16 + u]);
        }
        cp_commit();
    }

    const unsigned* hh32 = (const unsigned*)g_hh;
    const unsigned* hl32 = (const unsigned*)g_hl;
    unsigned ah[8][4], al[8][4];
#pragma unroll
    for (int kt = 0; kt < 8; kt++) {
        int b0 = row0 * 64 + qi + 8 * kt;
        int b1 = row1 * 64 + qi + 8 * kt;
        ah[kt][0] = hh32[b0];     ah[kt][1] = hh32[b1];
        ah[kt][2] = hh32[b0 + 4]; ah[kt][3] = hh32[b1 + 4];
        al[kt][0] = hl32[b0];     al[kt][1] = hl32[b1];
        al[kt][2] = hl32[b0 + 4]; al[kt][3] = hl32[b1 + 4];
    }

    float C[16][4];
#pragma unroll
    for (int nt = 0; nt < 16; nt++)
        C[nt][0] = C[nt][1] = C[nt][2] = C[nt][3] = 0.f;

    cp_wait<0>();
    __syncthreads();

#pragma unroll
    for (int kt = 0; kt < 8; kt++) {
#pragma unroll
        for (int g2 = 0; g2 < 4; g2++) {
            unsigned b0[4], b1[4], c0[4], c1[4];
#pragma unroll
            for (int i = 0; i < 4; i++) {
                int nt = 4 * g2 + i;
                int bi = (8 * nt + lr) * PSTRW + qi + 8 * kt;
                b0[i] = sBh[bi]; b1[i] = sBh[bi + 4];
                c0[i] = sBl[bi]; c1[i] = sBl[bi + 4];
            }
#pragma unroll
            for (int i = 0; i < 4; i++)
                mma_bf16(C[4*g2+i], ah[kt][0], ah[kt][1], ah[kt][2], ah[kt][3], b0[i], b1[i]);
#pragma unroll
            for (int i = 0; i < 4; i++)
                mma_bf16(C[4*g2+i], al[kt][0], al[kt][1], al[kt][2], al[kt][3], b0[i], b1[i]);
#pragma unroll
            for (int i = 0; i < 4; i++)
                mma_bf16(C[4*g2+i], ah[kt][0], ah[kt][1], ah[kt][2], ah[kt][3], c0[i], c1[i]);
        }
    }

    if (ntile == 0) {
#pragma unroll
        for (int nt = 0; nt < 16; nt++) {
            __nv_bfloat16 h0, l0, h1, l1, h2, l2, h3, l3;
            split_bf(C[nt][0], h0, l0); split_bf(C[nt][1], h1, l1);
            split_bf(C[nt][2], h2, l2); split_bf(C[nt][3], h3, l3);
            int col = 8 * nt + 2 * qi;
            __nv_bfloat16* dh = (col < 64) ? g_Qh : g_Kh;
            __nv_bfloat16* dl = (col < 64) ? g_Ql : g_Kl;
            int c = col & 63;
            *(unsigned*)&dh[(size_t)row0 * HID + c] = pack_bf2(h0, h1);
            *(unsigned*)&dl[(size_t)row0 * HID + c] = pack_bf2(l0, l1);
            *(unsigned*)&dh[(size_t)row1 * HID + c] = pack_bf2(h2, h3);
            *(unsigned*)&dl[(size_t)row1 * HID + c] = pack_bf2(l2, l3);
        }
    } else {
#pragma unroll
        for (int nt = 0; nt < 16; nt++) {
            int col = 8 * nt + 2 * qi;
            g_Vt[(size_t)col       * N_NODES + row0] = __float2half_rn(C[nt][0]);
            g_Vt[(size_t)(col + 1) * N_NODES + row0] = __float2half_rn(C[nt][1]);
            g_Vt[(size_t)col       * N_NODES + row1] = __float2half_rn(C[nt][2]);
            g_Vt[(size_t)(col + 1) * N_NODES + row1] = __float2half_rn(C[nt][3]);
        }
    }
}

// ---------------- flash attention (persistent, occ 2, S pipelined) ---------
// grid = 296 CTAs; CTA c owns flattened units [start(c), start(c+1)).
__global__ __launch_bounds__(128, 2)
void flash_kernel(const int* __restrict__ adj) {
    extern __shared__ __align__(16) unsigned char dynsmem[];
    uint4* base4 = (uint4*)dynsmem;

    const int tid  = threadIdx.x;
    const int warp = tid >> 5;
    const int lane = tid & 31;
    const int lr   = lane >> 2;
    const int qi   = lane & 3;

    const int c  = blockIdx.x;
    const int u0 = UNIT_Q * c + min(c, UNIT_R);
    const int u1 = u0 + UNIT_Q + (c < UNIT_R ? 1 : 0);

    const int2*  adj2 = (const int2*)adj;
    const uint4* gKh4 = (const uint4*)g_Kh;
    const uint4* gKl4 = (const uint4*)g_Kl;
    const uint4* gV4  = (const uint4*)g_Vt;
    const unsigned* qh32 = (const unsigned*)g_Qh;
    const unsigned* ql32 = (const unsigned*)g_Ql;

    int u = u0;
    while (u < u1) {
        const int t    = u >> 7;           // m-tile
        const int jb0  = u & 127;          // first j-block in this tile
        const int nit  = min(128 - jb0, u1 - u);
        const int slot = c - cfirst_of(t << 7);
        const int jbase = jb0 * BN;

        const int mr   = t * BM + warp * 16;
        const int row0 = mr + lr;
        const int row1 = row0 + 8;

        // Q fragments (hi/lo)
        unsigned qh[4][4], ql[4][4];
#pragma unroll
        for (int kt = 0; kt < 4; kt++) {
            int b0 = row0 * 32 + qi + 8 * kt;
            int b1 = row1 * 32 + qi + 8 * kt;
            qh[kt][0] = qh32[b0];     qh[kt][1] = qh32[b1];
            qh[kt][2] = qh32[b0 + 4]; qh[kt][3] = qh32[b1 + 4];
            ql[kt][0] = ql32[b0];     ql[kt][1] = ql32[b1];
            ql[kt][2] = ql32[b0 + 4]; ql[kt][3] = ql32[b1 + 4];
        }

        float O[16][4];
#pragma unroll
        for (int v = 0; v < 16; v++)
#pragma unroll
            for (int i = 0; i < 4; i++) O[v][i] = 0.f;
        float m0 = -1e30f, m1 = -1e30f, l0 = 0.f, l1 = 0.f;

        // segment prologue: previous segment's readers done before refill
        __syncthreads();
        {
            uint4* bKh = base4;
            uint4* bKl = base4 + 576;
            uint4* bV  = base4 + 1152;
#pragma unroll
            for (int i = tid; i < 512; i += 128) {
                int r = i >> 3, cw = i & 7;
                cp16(&bKh[r * KSTR4 + cw], &gKh4[(jbase + r) * 8 + cw]);
                cp16(&bKl[r * KSTR4 + cw], &gKl4[(jbase + r) * 8 + cw]);
            }
#pragma unroll
            for (int i = tid; i < 1024; i += 128) {
                int cl2 = i >> 3, kw = i & 7;
                cp16(&bV[cl2 * KSTR4 + kw], &gV4[cl2 * 1024 + (jbase >> 3) + kw]);
            }
            cp_commit();
        }
        if (nit > 1) {
            const int jn = jbase + BN;
            uint4* bKh = base4 + BUF_U4;
            uint4* bKl = bKh + 576;
            uint4* bV  = bKh + 1152;
#pragma unroll
            for (int i = tid; i < 512; i += 128) {
                int r = i >> 3, cw = i & 7;
                cp16(&bKh[r * KSTR4 + cw], &gKh4[(jn + r) * 8 + cw]);
                cp16(&bKl[r * KSTR4 + cw], &gKl4[(jn + r) * 8 + cw]);
            }
#pragma unroll
            for (int i = tid; i < 1024; i += 128) {
                int cl2 = i >> 3, kw = i & 7;
                cp16(&bV[cl2 * KSTR4 + kw], &gV4[cl2 * 1024 + (jn >> 3) + kw]);
            }
            cp_commit();
            cp_wait<1>();     // buffer 0 complete (buffer 1 may pend)
        } else {
            cp_wait<0>();
        }
        __syncthreads();

        // S(0) into SA
        float SA[8][4], SB[8][4];
        compute_S(SA, (const unsigned*)base4, (const unsigned*)base4 + 576 * 4,
                  qh, ql, lr, qi);

        int bc = 0;   // buffer of iteration it
        for (int it = 0; it < nit; ++it) {
            const int j0 = jbase + it * BN;
            int bn = bc + 1; if (bn == 3) bn = 0;    // buffer of it+1
            int bf = bn + 1; if (bf == 3) bf = 0;    // fill target (it+2)

            // adj -> 2-bit-per-column masks (frees 28 registers vs int2[16])
            unsigned bitsA = 0, bitsB = 0;
#pragma unroll
            for (int nt = 0; nt < 8; nt++) {
                int2 a = __ldcs(&adj2[row0 * 4096 + (j0 >> 1) + 4 * nt + qi]);
                int2 b = __ldcs(&adj2[row1 * 4096 + (j0 >> 1) + 4 * nt + qi]);
                bitsA |= (a.x > 0 ? 1u : 0u) << (2 * nt);
                bitsA |= (a.y > 0 ? 1u : 0u) << (2 * nt + 1);
                bitsB |= (b.x > 0 ? 1u : 0u) << (2 * nt);
                bitsB |= (b.y > 0 ? 1u : 0u) << (2 * nt + 1);
            }

            cp_wait<0>();      // fill(it+1) complete
            __syncthreads();   // visible to all; readers of b(it-1) done -> bf safe

            // fill buffer (it+2)
            if (it + 2 < nit) {
                const int jn = j0 + 2 * BN;
                uint4* bKh = base4 + bf * BUF_U4;
                uint4* bKl = bKh + 576;
                uint4* bV  = bKh + 1152;
#pragma unroll
                for (int i = tid; i < 512; i += 128) {
                    int r = i >> 3, cw = i & 7;
                    cp16(&bKh[r * KSTR4 + cw], &gKh4[(jn + r) * 8 + cw]);
                    cp16(&bKl[r * KSTR4 + cw], &gKl4[(jn + r) * 8 + cw]);
                }
#pragma unroll
                for (int i = tid; i < 1024; i += 128) {
                    int cl2 = i >> 3, kw = i & 7;
                    cp16(&bV[cl2 * KSTR4 + kw], &gV4[cl2 * 1024 + (jn >> 3) + kw]);
                }
                cp_commit();
            }

            // issue S(it+1) MMAs first: they drain in the tensor pipe while
            // this warp does the softmax math below.
            if (it + 1 < nit) {
                const unsigned* nKh32 = (const unsigned*)(base4 + bn * BUF_U4);
                compute_S(SB, nKh32, nKh32 + 576 * 4, qh, ql, lr, qi);
            }

            // ---- softmax on SA (iteration it) ---------------------------
            float rmax0 = -1e30f, rmax1 = -1e30f;
#pragma unroll
            for (int nt = 0; nt < 8; nt++) {
                if (!((bitsA >> (2 * nt)) & 1))     SA[nt][0] = -1e30f;
                if (!((bitsA >> (2 * nt + 1)) & 1)) SA[nt][1] = -1e30f;
                if (!((bitsB >> (2 * nt)) & 1))     SA[nt][2] = -1e30f;
                if (!((bitsB >> (2 * nt + 1)) & 1)) SA[nt][3] = -1e30f;
                rmax0 = fmaxf(rmax0, fmaxf(SA[nt][0], SA[nt][1]));
                rmax1 = fmaxf(rmax1, fmaxf(SA[nt][2], SA[nt][3]));
            }
            rmax0 = fmaxf(rmax0, __shfl_xor_sync(0xffffffffu, rmax0, 1));
            rmax0 = fmaxf(rmax0, __shfl_xor_sync(0xffffffffu, rmax0, 2));
            rmax1 = fmaxf(rmax1, __shfl_xor_sync(0xffffffffu, rmax1, 1));
            rmax1 = fmaxf(rmax1, __shfl_xor_sync(0xffffffffu, rmax1, 2));

            float mn0 = fmaxf(m0, rmax0), mn1 = fmaxf(m1, rmax1);
            float sc0 = __expf(m0 - mn0), sc1 = __expf(m1 - mn1);
            m0 = mn0; m1 = mn1;

            float rs0 = 0.f, rs1 = 0.f;
            unsigned ap[4][4];
#pragma unroll
            for (int kt2 = 0; kt2 < 4; kt2++) {
#pragma unroll
                for (int half = 0; half < 2; half++) {
                    int nt = 2 * kt2 + half;
                    float p0 = (SA[nt][0] > -1e29f) ? __expf(SA[nt][0] - mn0) : 0.f;
                    float p1 = (SA[nt][1] > -1e29f) ? __expf(SA[nt][1] - mn0) : 0.f;
                    float p2 = (SA[nt][2] > -1e29f) ? __expf(SA[nt][2] - mn1) : 0.f;
                    float p3 = (SA[nt][3] > -1e29f) ? __expf(SA[nt][3] - mn1) : 0.f;
                    rs0 += p0 + p1;
                    rs1 += p2 + p3;
                    ap[kt2][2 * half + 0] = pack_h2(__float2half_rn(p0), __float2half_rn(p1));
                    ap[kt2][2 * half + 1] = pack_h2(__float2half_rn(p2), __float2half_rn(p3));
                }
            }

            rs0 += __shfl_xor_sync(0xffffffffu, rs0, 1);
            rs0 += __shfl_xor_sync(0xffffffffu, rs0, 2);
            rs1 += __shfl_xor_sync(0xffffffffu, rs1, 1);
            rs1 += __shfl_xor_sync(0xffffffffu, rs1, 2);
            l0 = l0 * sc0 + rs0;
            l1 = l1 * sc1 + rs1;

            if (!__all_sync(0xffffffffu, (sc0 == 1.f) & (sc1 == 1.f))) {
#pragma unroll
                for (int v = 0; v < 16; v++) {
                    O[v][0] *= sc0; O[v][1] *= sc0;
                    O[v][2] *= sc1; O[v][3] *= sc1;
                }
            }

            // ---- O += P V (single fp16 term, chains interleaved x4) -----
            const unsigned* sV32 = (const unsigned*)(base4 + bc * BUF_U4) + 1152 * 4;
#pragma unroll
            for (int kt2 = 0; kt2 < 4; kt2++) {
#pragma unroll
                for (int gr = 0; gr < 4; gr++) {
                    unsigned v0[4], v1[4];
#pragma unroll
                    for (int i = 0; i < 4; i++) {
                        int vn = 4 * gr + i;
                        int bi = (8 * vn + lr) * KSTRW + qi + 8 * kt2;
                        v0[i] = sV32[bi]; v1[i] = sV32[bi + 4];
                    }
#pragma unroll
                    for (int i = 0; i < 4; i++)
                        mma_f16(O[4*gr+i], ap[kt2][0], ap[kt2][1], ap[kt2][2], ap[kt2][3], v0[i], v1[i]);
                }
            }

            // rotate: SA <- SB (32 MOVs; stalls only if S(it+1) not yet done)
            if (it + 1 < nit) {
#pragma unroll
                for (int nt = 0; nt < 8; nt++) {
                    SA[nt][0] = SB[nt][0]; SA[nt][1] = SB[nt][1];
                    SA[nt][2] = SB[nt][2]; SA[nt][3] = SB[nt][3];
                }
            }
            bc = bn;
        }

        // ---- store normalized partials (fp16) + (m, l) -------------------
        float inv0 = (l0 > 0.f) ? 1.f / l0 : 0.f;
        float inv1 = (l1 > 0.f) ? 1.f / l1 : 0.f;
        __half* oph = &g_Oph[slot][0][0];
#pragma unroll
        for (int vn = 0; vn < 16; vn++) {
            int col = 8 * vn + 2 * qi;
            *(unsigned*)&oph[row0 * OUT_F + col] =
                pack_h2(__float2half_rn(O[vn][0] * inv0), __float2half_rn(O[vn][1] * inv0));
            *(unsigned*)&oph[row1 * OUT_F + col] =
                pack_h2(__float2half_rn(O[vn][2] * inv1), __float2half_rn(O[vn][3] * inv1));
        }
        if (qi == 0) {
            g_pm[slot][row0] = m0; g_pl[slot][row0] = l0;
            g_pm[slot][row1] = m1; g_pl[slot][row1] = l1;
        }

        u += nit;
    }
}

// ---------------- merge partial slots (weights l_s * exp(m_s - M)) ---------
// grid 1024 x 256: block = 8 rows, thread = 4 cols
__global__ __launch_bounds__(256)
void merge_kernel(float* __restrict__ out) {
    const int row = blockIdx.x * 8 + (threadIdx.x >> 5);
    const int cc  = (threadIdx.x & 31) * 4;

    const int t  = row >> 6;
    const int ut = t << 7;
    const int ns = cfirst_of(ut + 127) - cfirst_of(ut) + 1;   // 2..4

    float ms[SLOTS], ls[SLOTS];
#pragma unroll
    for (int s = 0; s < SLOTS; s++) {
        bool ok = (s < ns);
        ms[s] = ok ? g_pm[s][row] : -1e30f;
        ls[s] = ok ? g_pl[s][row] : 0.f;
    }
    float M = fmaxf(fmaxf(ms[0], ms[1]), fmaxf(ms[2], ms[3]));

    float acc[4] = {0.f, 0.f, 0.f, 0.f};
    float den = 0.f;
#pragma unroll
    for (int s = 0; s < SLOTS; s++) {
        float w = ls[s] * __expf(ms[s] - M);
        den += w;
        uint2 pv = *(const uint2*)&g_Oph[s][row][cc];
        __half2 h01 = *(__half2*)&pv.x;
        __half2 h23 = *(__half2*)&pv.y;
        acc[0] += w * __half2float(__low2half(h01));
        acc[1] += w * __half2float(__high2half(h01));
        acc[2] += w * __half2float(__low2half(h23));
        acc[3] += w * __half2float(__high2half(h23));
    }
    float inv = 1.f / den;
    *(float4*)&out[row * OUT_F + cc] =
        make_float4(acc[0] * inv, acc[1] * inv, acc[2] * inv, acc[3] * inv);
}

// ---------------- launch --------------------------------------------------
extern "C" void kernel_launch(void* const* d_in, const int* in_sizes, int n_in,
                              void* d_out, int out_size) {
    const float* h   = (const float*)d_in[0];
    const int*   adj = (const int*)d_in[1];
    const float* Ws  = (const float*)d_in[2];
    const float* Wt  = (const float*)d_in[3];
    const float* Wc  = (const float*)d_in[4];
    float* out = (float*)d_out;

    split_kernel<<<544, 256>>>(h, Ws, Wt, Wc);

    cudaFuncSetAttribute(gemm_prep,
                         cudaFuncAttributeMaxDynamicSharedMemorySize, PREP_SMEM);
    gemm_prep<<<256, 128, PREP_SMEM>>>();

    cudaFuncSetAttribute(flash_kernel,
                         cudaFuncAttributeMaxDynamicSharedMemorySize, FLASH_SMEM);
    flash_kernel<<<N_CTAS, 128, FLASH_SMEM>>>(adj);

    merge_kernel<<<N_NODES / 8, 256>>>(out);
}

// round 15
// speedup vs baseline: 1.0261x; 1.0183x over previous
#include <cuda_runtime.h>
#include <cuda_bf16.h>
#include <cuda_fp16.h>
#include <cstdint>

#define N_NODES 8192
#define IN_F    128
#define HID     64
#define OUT_F   128
#define BM      64
#define BN      64

// persistent schedule: 16384 units = 128 mtiles x 128 jblocks, 296 CTAs
// start(c) = 55c + min(c,104)  (CTAs 0..103 have 56 units, rest 55)
#define N_CTAS  296
#define UNIT_Q  55
#define UNIT_R  104
#define CF_THRESH 5824   // start(104)
#define SLOTS   4

// K/V row stride in flash smem: 64 elems + 8 pad = 72 x 2B = 36 words = 9 uint4.
#define KSTRW 36
#define KSTR4 9
// uint4 per buffer: Kh 576, Kl 576, V 1152 -> 2304 u4 = 36864 B ; 3 buffers
#define BUF_U4 2304
#define FLASH_SMEM (3 * BUF_U4 * 16)   // 110592 B -> 2 CTAs/SM

// gemm_prep smem B row stride: 128 bf16 = 64 words data + 4 pad = 68 words = 17 u4
#define PSTRW 68
#define PSTR4 17
#define PREP_SMEM (2 * 128 * PSTRW * 4)   // Bh + Bl = 69632 B

// ---------------- scratch (static device globals; no allocs allowed) -----
__device__ __align__(16) __nv_bfloat16 g_Wth[256 * IN_F];      // Wcat^T hi [col][k]
__device__ __align__(16) __nv_bfloat16 g_Wtl[256 * IN_F];      // Wcat^T lo
__device__ __align__(16) __nv_bfloat16 g_Qh[N_NODES * HID];
__device__ __align__(16) __nv_bfloat16 g_Ql[N_NODES * HID];
__device__ __align__(16) __nv_bfloat16 g_Kh[N_NODES * HID];
__device__ __align__(16) __nv_bfloat16 g_Kl[N_NODES * HID];
__device__ __align__(16) __half g_Vt[OUT_F * N_NODES];         // V^T fp16 [feat][j]
// partial slots per m-tile: NORMALIZED O in fp16 + (m, l) in fp32
__device__ __align__(16) __half g_Oph[SLOTS][N_NODES][OUT_F];
__device__ float g_pm[SLOTS][N_NODES];
__device__ float g_pl[SLOTS][N_NODES];

// ---------------- helpers --------------------------------------------------
__device__ __forceinline__ void cp16(void* s, const void* g) {
    unsigned sa = (unsigned)__cvta_generic_to_shared(s);
    asm volatile("cp.async.cg.shared.global [%0], [%1], 16;\n" :: "r"(sa), "l"(g));
}
__device__ __forceinline__ void cp_commit() { asm volatile("cp.async.commit_group;\n"); }
template <int N> __device__ __forceinline__ void cp_wait() {
    asm volatile("cp.async.wait_group %0;\n" :: "n"(N));
}
__device__ __forceinline__ void mma_bf16(float c[4],
                                         unsigned a0, unsigned a1, unsigned a2, unsigned a3,
                                         unsigned b0, unsigned b1) {
    asm volatile(
        "mma.sync.aligned.m16n8k16.row.col.f32.bf16.bf16.f32 "
        "{%0,%1,%2,%3}, {%4,%5,%6,%7}, {%8,%9}, {%0,%1,%2,%3};\n"
        : "+f"(c[0]), "+f"(c[1]), "+f"(c[2]), "+f"(c[3])
        : "r"(a0), "r"(a1), "r"(a2), "r"(a3), "r"(b0), "r"(b1));
}
__device__ __forceinline__ void mma_f16(float c[4],
                                        unsigned a0, unsigned a1, unsigned a2, unsigned a3,
                                        unsigned b0, unsigned b1) {
    asm volatile(
        "mma.sync.aligned.m16n8k16.row.col.f32.f16.f16.f32 "
        "{%0,%1,%2,%3}, {%4,%5,%6,%7}, {%8,%9}, {%0,%1,%2,%3};\n"
        : "+f"(c[0]), "+f"(c[1]), "+f"(c[2]), "+f"(c[3])
        : "r"(a0), "r"(a1), "r"(a2), "r"(a3), "r"(b0), "r"(b1));
}
__device__ __forceinline__ unsigned pack_bf2(__nv_bfloat16 a, __nv_bfloat16 b) {
    return (unsigned)__bfloat16_as_ushort(a) |
           ((unsigned)__bfloat16_as_ushort(b) << 16);
}
__device__ __forceinline__ unsigned pack_h2(__half a, __half b) {
    return (unsigned)__half_as_ushort(a) |
           ((unsigned)__half_as_ushort(b) << 16);
}
__device__ __forceinline__ void split_bf(float v, __nv_bfloat16& hi, __nv_bfloat16& lo) {
    hi = __float2bfloat16(v);
    lo = __float2bfloat16(v - __bfloat162float(hi));
}
// split a float2 (two consecutive k-values) into packed hi / lo words
__device__ __forceinline__ void split_pack2(float2 v, unsigned& ph, unsigned& pl) {
    __nv_bfloat16 h0, l0, h1, l1;
    split_bf(v.x, h0, l0);
    split_bf(v.y, h1, l1);
    ph = pack_bf2(h0, h1);
    pl = pack_bf2(l0, l1);
}
__device__ __forceinline__ int cfirst_of(int ut) {
    return (ut < CF_THRESH) ? (ut / 56) : ((ut - UNIT_R) / UNIT_Q);
}

// ---------------- split: Wcat^T -> bf16 hi/lo (W only; h handled in prep) --
// grid 32 x 256: t = col*32 + k-quarter
__global__ __launch_bounds__(256)
void split_kernel(const float* __restrict__ Ws,
                  const float* __restrict__ Wt,
                  const float* __restrict__ Wc) {
    int t  = blockIdx.x * 256 + threadIdx.x;    // 0..8191
    int c  = t >> 5;                            // concat col 0..255
    int k0 = (t & 31) * 4;
    const float* W; int stride, cc;
    if (c < 64)       { W = Ws; stride = 64;  cc = c; }
    else if (c < 128) { W = Wt; stride = 64;  cc = c - 64; }
    else              { W = Wc; stride = 128; cc = c - 128; }
    union { __nv_bfloat16 b[4]; uint2 u; } ph, pl;
#pragma unroll
    for (int j = 0; j < 4; j++)
        split_bf(W[(k0 + j) * stride + cc], ph.b[j], pl.b[j]);
    *(uint2*)(g_Wth + c * IN_F + k0) = ph.u;
    *(uint2*)(g_Wtl + c * IN_F + k0) = pl.u;
}

// ---------------- gemm_prep: C = h @ Wcat (3-term bf16), fp32 h in-kernel --
// grid 256: mtile = bx & 127 (64 rows), ntile = bx >> 7 (128 cols). 128 threads.
__global__ __launch_bounds__(128, 2)
void gemm_prep(const float* __restrict__ h) {
    extern __shared__ __align__(16) unsigned char psmem[];
    unsigned* sBh = (unsigned*)psmem;                    // [128][68 words]
    unsigned* sBl = sBh + 128 * PSTRW;

    const int tid  = threadIdx.x;
    const int warp = tid >> 5;
    const int lane = tid & 31;
    const int lr   = lane >> 2;
    const int qi   = lane & 3;

    const int mtile = blockIdx.x & 127;
    const int ntile = blockIdx.x >> 7;
    const int row0  = mtile * 64 + warp * 16 + lr;
    const int row1  = row0 + 8;

    // B tile fill via cp.async (overlaps the fp32 A loads below)
    {
        const uint4* gWh4 = (const uint4*)g_Wth;
        const uint4* gWl4 = (const uint4*)g_Wtl;
        uint4* sBh4 = (uint4*)sBh;
        uint4* sBl4 = (uint4*)sBl;
#pragma unroll
        for (int i = tid; i < 2048; i += 128) {
            int r = i >> 4, u = i & 15;
            cp16(&sBh4[r * PSTR4 + u], &gWh4[(ntile * 128 + r) * 16 + u]);
            cp16(&sBl4[r * PSTR4 + u], &gWl4[(ntile * 128 + r) * 16 + u]);
        }
        cp_commit();
    }

    // A fragments from fp32 h, split in registers.
    // word w of a row covers h cols {2w, 2w+1}; fragment words w = qi+8kt, +4.
    const float* h0p = h + (size_t)row0 * IN_F;
    const float* h1p = h + (size_t)row1 * IN_F;
    unsigned ah[8][4], al[8][4];
#pragma unroll
    for (int kt = 0; kt < 8; kt++) {
        int k = 2 * qi + 16 * kt;
        split_pack2(*(const float2*)&h0p[k],     ah[kt][0], al[kt][0]);
        split_pack2(*(const float2*)&h1p[k],     ah[kt][1], al[kt][1]);
        split_pack2(*(const float2*)&h0p[k + 8], ah[kt][2], al[kt][2]);
        split_pack2(*(const float2*)&h1p[k + 8], ah[kt][3], al[kt][3]);
    }

    float C[16][4];
#pragma unroll
    for (int nt = 0; nt < 16; nt++)
        C[nt][0] = C[nt][1] = C[nt][2] = C[nt][3] = 0.f;

    cp_wait<0>();
    __syncthreads();

#pragma unroll
    for (int kt = 0; kt < 8; kt++) {
#pragma unroll
        for (int g2 = 0; g2 < 4; g2++) {
            unsigned b0[4], b1[4], c0[4], c1[4];
#pragma unroll
            for (int i = 0; i < 4; i++) {
                int nt = 4 * g2 + i;
                int bi = (8 * nt + lr) * PSTRW + qi + 8 * kt;
                b0[i] = sBh[bi]; b1[i] = sBh[bi + 4];
                c0[i] = sBl[bi]; c1[i] = sBl[bi + 4];
            }
#pragma unroll
            for (int i = 0; i < 4; i++)
                mma_bf16(C[4*g2+i], ah[kt][0], ah[kt][1], ah[kt][2], ah[kt][3], b0[i], b1[i]);
#pragma unroll
            for (int i = 0; i < 4; i++)
                mma_bf16(C[4*g2+i], al[kt][0], al[kt][1], al[kt][2], al[kt][3], b0[i], b1[i]);
#pragma unroll
            for (int i = 0; i < 4; i++)
                mma_bf16(C[4*g2+i], ah[kt][0], ah[kt][1], ah[kt][2], ah[kt][3], c0[i], c1[i]);
        }
    }

    if (ntile == 0) {
#pragma unroll
        for (int nt = 0; nt < 16; nt++) {
            __nv_bfloat16 h0, l0, h1, l1, h2, l2, h3, l3;
            split_bf(C[nt][0], h0, l0); split_bf(C[nt][1], h1, l1);
            split_bf(C[nt][2], h2, l2); split_bf(C[nt][3], h3, l3);
            int col = 8 * nt + 2 * qi;
            __nv_bfloat16* dh = (col < 64) ? g_Qh : g_Kh;
            __nv_bfloat16* dl = (col < 64) ? g_Ql : g_Kl;
            int c = col & 63;
            *(unsigned*)&dh[(size_t)row0 * HID + c] = pack_bf2(h0, h1);
            *(unsigned*)&dl[(size_t)row0 * HID + c] = pack_bf2(l0, l1);
            *(unsigned*)&dh[(size_t)row1 * HID + c] = pack_bf2(h2, h3);
            *(unsigned*)&dl[(size_t)row1 * HID + c] = pack_bf2(l2, l3);
        }
    } else {
#pragma unroll
        for (int nt = 0; nt < 16; nt++) {
            int col = 8 * nt + 2 * qi;
            g_Vt[(size_t)col       * N_NODES + row0] = __float2half_rn(C[nt][0]);
            g_Vt[(size_t)(col + 1) * N_NODES + row0] = __float2half_rn(C[nt][1]);
            g_Vt[(size_t)col       * N_NODES + row1] = __float2half_rn(C[nt][2]);
            g_Vt[(size_t)(col + 1) * N_NODES + row1] = __float2half_rn(C[nt][3]);
        }
    }
}

// ---------------- flash attention (persistent, occ 2 — R10 config) ---------
// grid = 296 CTAs; CTA c owns flattened units [start(c), start(c+1)).
__global__ __launch_bounds__(128, 2)
void flash_kernel(const int* __restrict__ adj) {
    extern __shared__ __align__(16) unsigned char dynsmem[];
    uint4* base4 = (uint4*)dynsmem;

    const int tid  = threadIdx.x;
    const int warp = tid >> 5;
    const int lane = tid & 31;
    const int lr   = lane >> 2;
    const int qi   = lane & 3;

    const int c  = blockIdx.x;
    const int u0 = UNIT_Q * c + min(c, UNIT_R);
    const int u1 = u0 + UNIT_Q + (c < UNIT_R ? 1 : 0);

    const int2*  adj2 = (const int2*)adj;
    const uint4* gKh4 = (const uint4*)g_Kh;
    const uint4* gKl4 = (const uint4*)g_Kl;
    const uint4* gV4  = (const uint4*)g_Vt;
    const unsigned* qh32 = (const unsigned*)g_Qh;
    const unsigned* ql32 = (const unsigned*)g_Ql;

    int u = u0;
    while (u < u1) {
        const int t    = u >> 7;           // m-tile
        const int jb0  = u & 127;          // first j-block in this tile
        const int nit  = min(128 - jb0, u1 - u);
        const int slot = c - cfirst_of(t << 7);
        const int jbase = jb0 * BN;

        const int mr   = t * BM + warp * 16;
        const int row0 = mr + lr;
        const int row1 = row0 + 8;

        // Q fragments (hi/lo)
        unsigned qh[4][4], ql[4][4];
#pragma unroll
        for (int kt = 0; kt < 4; kt++) {
            int b0 = row0 * 32 + qi + 8 * kt;
            int b1 = row1 * 32 + qi + 8 * kt;
            qh[kt][0] = qh32[b0];     qh[kt][1] = qh32[b1];
            qh[kt][2] = qh32[b0 + 4]; qh[kt][3] = qh32[b1 + 4];
            ql[kt][0] = ql32[b0];     ql[kt][1] = ql32[b1];
            ql[kt][2] = ql32[b0 + 4]; ql[kt][3] = ql32[b1 + 4];
        }

        float O[16][4];
#pragma unroll
        for (int v = 0; v < 16; v++)
#pragma unroll
            for (int i = 0; i < 4; i++) O[v][i] = 0.f;
        float m0 = -1e30f, m1 = -1e30f, l0 = 0.f, l1 = 0.f;

        // segment prologue: prior segment done before refill
        __syncthreads();
        {
            uint4* bKh = base4;
            uint4* bKl = base4 + 576;
            uint4* bV  = base4 + 1152;
#pragma unroll
            for (int i = tid; i < 512; i += 128) {
                int r = i >> 3, cw = i & 7;
                cp16(&bKh[r * KSTR4 + cw], &gKh4[(jbase + r) * 8 + cw]);
                cp16(&bKl[r * KSTR4 + cw], &gKl4[(jbase + r) * 8 + cw]);
            }
#pragma unroll
            for (int i = tid; i < 1024; i += 128) {
                int cl2 = i >> 3, kw = i & 7;
                cp16(&bV[cl2 * KSTR4 + kw], &gV4[cl2 * 1024 + (jbase >> 3) + kw]);
            }
            cp_commit();
        }

        int b_cur = 0;
        for (int it = 0; it < nit; ++it) {
            const int j0 = jbase + it * BN;

            int2 adjA[8], adjB[8];
#pragma unroll
            for (int nt = 0; nt < 8; nt++) {
                adjA[nt] = __ldcs(&adj2[row0 * 4096 + (j0 >> 1) + 4 * nt + qi]);
                adjB[nt] = __ldcs(&adj2[row1 * 4096 + (j0 >> 1) + 4 * nt + qi]);
            }

            cp_wait<0>();
            __syncthreads();   // single barrier per iter (3-buffer reuse distance 2)

            if (it + 1 < nit) {
                const int jn = j0 + BN;
                const int b_nxt = (b_cur == 2) ? 0 : b_cur + 1;
                uint4* bKh = base4 + b_nxt * BUF_U4;
                uint4* bKl = bKh + 576;
                uint4* bV  = bKh + 1152;
#pragma unroll
                for (int i = tid; i < 512; i += 128) {
                    int r = i >> 3, cw = i & 7;
                    cp16(&bKh[r * KSTR4 + cw], &gKh4[(jn + r) * 8 + cw]);
                    cp16(&bKl[r * KSTR4 + cw], &gKl4[(jn + r) * 8 + cw]);
                }
#pragma unroll
                for (int i = tid; i < 1024; i += 128) {
                    int cl2 = i >> 3, kw = i & 7;
                    cp16(&bV[cl2 * KSTR4 + kw], &gV4[cl2 * 1024 + (jn >> 3) + kw]);
                }
                cp_commit();
            }

            const unsigned* sKh32 = (const unsigned*)(base4 + b_cur * BUF_U4);
            const unsigned* sKl32 = sKh32 + 576 * 4;
            const unsigned* sV32  = sKh32 + 1152 * 4;

            // S = Q K^T (3-term bf16 split, chains interleaved x4)
            float S[8][4];
#pragma unroll
            for (int nt = 0; nt < 8; nt++)
                S[nt][0] = S[nt][1] = S[nt][2] = S[nt][3] = 0.f;

#pragma unroll
            for (int kt = 0; kt < 4; kt++) {
#pragma unroll
                for (int gr = 0; gr < 2; gr++) {
                    unsigned b0[4], b1[4], c0[4], c1[4];
#pragma unroll
                    for (int i = 0; i < 4; i++) {
                        int nt = 4 * gr + i;
                        int bi = (8 * nt + lr) * KSTRW + qi + 8 * kt;
                        b0[i] = sKh32[bi]; b1[i] = sKh32[bi + 4];
                        c0[i] = sKl32[bi]; c1[i] = sKl32[bi + 4];
                    }
#pragma unroll
                    for (int i = 0; i < 4; i++)
                        mma_bf16(S[4*gr+i], qh[kt][0], qh[kt][1], qh[kt][2], qh[kt][3], b0[i], b1[i]);
#pragma unroll
                    for (int i = 0; i < 4; i++)
                        mma_bf16(S[4*gr+i], ql[kt][0], ql[kt][1], ql[kt][2], ql[kt][3], b0[i], b1[i]);
#pragma unroll
                    for (int i = 0; i < 4; i++)
                        mma_bf16(S[4*gr+i], qh[kt][0], qh[kt][1], qh[kt][2], qh[kt][3], c0[i], c1[i]);
                }
            }

            // mask + row max
            float rmax0 = -1e30f, rmax1 = -1e30f;
#pragma unroll
            for (int nt = 0; nt < 8; nt++) {
                if (adjA[nt].x <= 0) S[nt][0] = -1e30f;
                if (adjA[nt].y <= 0) S[nt][1] = -1e30f;
                if (adjB[nt].x <= 0) S[nt][2] = -1e30f;
                if (adjB[nt].y <= 0) S[nt][3] = -1e30f;
                rmax0 = fmaxf(rmax0, fmaxf(S[nt][0], S[nt][1]));
                rmax1 = fmaxf(rmax1, fmaxf(S[nt][2], S[nt][3]));
            }
            rmax0 = fmaxf(rmax0, __shfl_xor_sync(0xffffffffu, rmax0, 1));
            rmax0 = fmaxf(rmax0, __shfl_xor_sync(0xffffffffu, rmax0, 2));
            rmax1 = fmaxf(rmax1, __shfl_xor_sync(0xffffffffu, rmax1, 1));
            rmax1 = fmaxf(rmax1, __shfl_xor_sync(0xffffffffu, rmax1, 2));

            float mn0 = fmaxf(m0, rmax0), mn1 = fmaxf(m1, rmax1);
            float sc0 = __expf(m0 - mn0), sc1 = __expf(m1 - mn1);
            m0 = mn0; m1 = mn1;

            // exp + pack P (fp16)
            float rs0 = 0.f, rs1 = 0.f;
            unsigned ap[4][4];
#pragma unroll
            for (int kt2 = 0; kt2 < 4; kt2++) {
#pragma unroll
                for (int half = 0; half < 2; half++) {
                    int nt = 2 * kt2 + half;
                    float p0 = (S[nt][0] > -1e29f) ? __expf(S[nt][0] - mn0) : 0.f;
                    float p1 = (S[nt][1] > -1e29f) ? __expf(S[nt][1] - mn0) : 0.f;
                    float p2 = (S[nt][2] > -1e29f) ? __expf(S[nt][2] - mn1) : 0.f;
                    float p3 = (S[nt][3] > -1e29f) ? __expf(S[nt][3] - mn1) : 0.f;
                    rs0 += p0 + p1;
                    rs1 += p2 + p3;
                    ap[kt2][2 * half + 0] = pack_h2(__float2half_rn(p0), __float2half_rn(p1));
                    ap[kt2][2 * half + 1] = pack_h2(__float2half_rn(p2), __float2half_rn(p3));
                }
            }

            rs0 += __shfl_xor_sync(0xffffffffu, rs0, 1);
            rs0 += __shfl_xor_sync(0xffffffffu, rs0, 2);
            rs1 += __shfl_xor_sync(0xffffffffu, rs1, 1);
            rs1 += __shfl_xor_sync(0xffffffffu, rs1, 2);
            l0 = l0 * sc0 + rs0;
            l1 = l1 * sc1 + rs1;

            if (!__all_sync(0xffffffffu, (sc0 == 1.f) & (sc1 == 1.f))) {
#pragma unroll
                for (int v = 0; v < 16; v++) {
                    O[v][0] *= sc0; O[v][1] *= sc0;
                    O[v][2] *= sc1; O[v][3] *= sc1;
                }
            }

            // O += P V (single fp16 term, chains interleaved x4)
#pragma unroll
            for (int kt2 = 0; kt2 < 4; kt2++) {
#pragma unroll
                for (int gr = 0; gr < 4; gr++) {
                    unsigned v0[4], v1[4];
#pragma unroll
                    for (int i = 0; i < 4; i++) {
                        int vn = 4 * gr + i;
                        int bi = (8 * vn + lr) * KSTRW + qi + 8 * kt2;
                        v0[i] = sV32[bi]; v1[i] = sV32[bi + 4];
                    }
#pragma unroll
                    for (int i = 0; i < 4; i++)
                        mma_f16(O[4*gr+i], ap[kt2][0], ap[kt2][1], ap[kt2][2], ap[kt2][3], v0[i], v1[i]);
                }
            }

            b_cur = (b_cur == 2) ? 0 : b_cur + 1;
        }

        // store NORMALIZED partials (fp16) + (m, l)
        float inv0 = (l0 > 0.f) ? 1.f / l0 : 0.f;
        float inv1 = (l1 > 0.f) ? 1.f / l1 : 0.f;
        __half* oph = &g_Oph[slot][0][0];
#pragma unroll
        for (int vn = 0; vn < 16; vn++) {
            int col = 8 * vn + 2 * qi;
            *(unsigned*)&oph[row0 * OUT_F + col] =
                pack_h2(__float2half_rn(O[vn][0] * inv0), __float2half_rn(O[vn][1] * inv0));
            *(unsigned*)&oph[row1 * OUT_F + col] =
                pack_h2(__float2half_rn(O[vn][2] * inv1), __float2half_rn(O[vn][3] * inv1));
        }
        if (qi == 0) {
            g_pm[slot][row0] = m0; g_pl[slot][row0] = l0;
            g_pm[slot][row1] = m1; g_pl[slot][row1] = l1;
        }

        u += nit;
    }
}

// ---------------- merge partial slots (conditional, weights l_s e^{m_s-M}) -
// grid 1024 x 256: block = 8 rows, thread = 4 cols
__global__ __launch_bounds__(256)
void merge_kernel(float* __restrict__ out) {
    const int row = blockIdx.x * 8 + (threadIdx.x >> 5);
    const int cc  = (threadIdx.x & 31) * 4;

    const int t  = row >> 6;
    const int ut = t << 7;
    const int ns = cfirst_of(ut + 127) - cfirst_of(ut) + 1;   // 2..4

    float ms[SLOTS], ls[SLOTS];
    float M = -1e30f;
    for (int s = 0; s < ns; s++) {
        ms[s] = g_pm[s][row];
        ls[s] = g_pl[s][row];
        M = fmaxf(M, ms[s]);
    }

    float acc0 = 0.f, acc1 = 0.f, acc2 = 0.f, acc3 = 0.f, den = 0.f;
    for (int s = 0; s < ns; s++) {
        float w = ls[s] * __expf(ms[s] - M);
        den += w;
        uint2 pv = *(const uint2*)&g_Oph[s][row][cc];
        __half2 h01 = *(__half2*)&pv.x;
        __half2 h23 = *(__half2*)&pv.y;
        acc0 += w * __half2float(__low2half(h01));
        acc1 += w * __half2float(__high2half(h01));
        acc2 += w * __half2float(__low2half(h23));
        acc3 += w * __half2float(__high2half(h23));
    }
    float inv = 1.f / den;
    *(float4*)&out[row * OUT_F + cc] =
        make_float4(acc0 * inv, acc1 * inv, acc2 * inv, acc3 * inv);
}

// ---------------- launch --------------------------------------------------
extern "C" void kernel_launch(void* const* d_in, const int* in_sizes, int n_in,
                              void* d_out, int out_size) {
    const float* h   = (const float*)d_in[0];
    const int*   adj = (const int*)d_in[1];
    const float* Ws  = (const float*)d_in[2];
    const float* Wt  = (const float*)d_in[3];
    const float* Wc  = (const float*)d_in[4];
    float* out = (float*)d_out;

    split_kernel<<<32, 256>>>(Ws, Wt, Wc);

    cudaFuncSetAttribute(gemm_prep,
                         cudaFuncAttributeMaxDynamicSharedMemorySize, PREP_SMEM);
    gemm_prep<<<256, 128, PREP_SMEM>>>(h);

    cudaFuncSetAttribute(flash_kernel,
                         cudaFuncAttributeMaxDynamicSharedMemorySize, FLASH_SMEM);
    flash_kernel<<<N_CTAS, 128, FLASH_SMEM>>>(adj);

    merge_kernel<<<N_NODES / 8, 256>>>(out);
}

// round 16
// speedup vs baseline: 1.0285x; 1.0023x over previous
#include <cuda_runtime.h>
#include <cuda_bf16.h>
#include <cuda_fp16.h>
#include <cstdint>

#define N_NODES 8192
#define IN_F    128
#define HID     64
#define OUT_F   128
#define BM      64
#define BN      64

// persistent schedule: 16384 units = 128 mtiles x 128 jblocks, 296 CTAs
// start(c) = 55c + min(c,104)  (CTAs 0..103 have 56 units, rest 55)
#define N_CTAS  296
#define UNIT_Q  55
#define UNIT_R  104
#define CF_THRESH 5824   // start(104)
#define SLOTS   4

// K/V row stride in flash smem: 64 elems + 8 pad = 72 x 2B = 36 words = 9 uint4.
#define KSTRW 36
#define KSTR4 9
// uint4 per buffer: Kh 576, Kl 576, V 1152 -> 2304 u4 = 36864 B ; 3 buffers
#define BUF_U4 2304
#define FLASH_SMEM (3 * BUF_U4 * 16)   // 110592 B -> 2 CTAs/SM

// gemm_prep smem B row stride: 128 bf16 = 64 words data + 4 pad = 68 words = 17 u4
#define PSTRW 68
#define PSTR4 17
#define PREP_SMEM (2 * 128 * PSTRW * 4)   // Bh + Bl = 69632 B

// ---------------- scratch (static device globals; no allocs allowed) -----
__device__ __align__(16) __nv_bfloat16 g_Wth[256 * IN_F];      // Wcat^T hi [col][k]
__device__ __align__(16) __nv_bfloat16 g_Wtl[256 * IN_F];      // Wcat^T lo
__device__ __align__(16) __nv_bfloat16 g_Qh[N_NODES * HID];
__device__ __align__(16) __nv_bfloat16 g_Ql[N_NODES * HID];
__device__ __align__(16) __nv_bfloat16 g_Kh[N_NODES * HID];
__device__ __align__(16) __nv_bfloat16 g_Kl[N_NODES * HID];
__device__ __align__(16) __half g_Vt[OUT_F * N_NODES];         // V^T fp16 [feat][j]
// partial slots per m-tile: NORMALIZED O in fp16 + (m, l) in fp32
__device__ __align__(16) __half g_Oph[SLOTS][N_NODES][OUT_F];
__device__ float g_pm[SLOTS][N_NODES];
__device__ float g_pl[SLOTS][N_NODES];

// ---------------- helpers --------------------------------------------------
__device__ __forceinline__ void cp16(void* s, const void* g) {
    unsigned sa = (unsigned)__cvta_generic_to_shared(s);
    asm volatile("cp.async.cg.shared.global [%0], [%1], 16;\n" :: "r"(sa), "l"(g));
}
__device__ __forceinline__ void cp_commit() { asm volatile("cp.async.commit_group;\n"); }
template <int N> __device__ __forceinline__ void cp_wait() {
    asm volatile("cp.async.wait_group %0;\n" :: "n"(N));
}
__device__ __forceinline__ void mma_bf16(float c[4],
                                         unsigned a0, unsigned a1, unsigned a2, unsigned a3,
                                         unsigned b0, unsigned b1) {
    asm volatile(
        "mma.sync.aligned.m16n8k16.row.col.f32.bf16.bf16.f32 "
        "{%0,%1,%2,%3}, {%4,%5,%6,%7}, {%8,%9}, {%0,%1,%2,%3};\n"
        : "+f"(c[0]), "+f"(c[1]), "+f"(c[2]), "+f"(c[3])
        : "r"(a0), "r"(a1), "r"(a2), "r"(a3), "r"(b0), "r"(b1));
}
__device__ __forceinline__ void mma_f16(float c[4],
                                        unsigned a0, unsigned a1, unsigned a2, unsigned a3,
                                        unsigned b0, unsigned b1) {
    asm volatile(
        "mma.sync.aligned.m16n8k16.row.col.f32.f16.f16.f32 "
        "{%0,%1,%2,%3}, {%4,%5,%6,%7}, {%8,%9}, {%0,%1,%2,%3};\n"
        : "+f"(c[0]), "+f"(c[1]), "+f"(c[2]), "+f"(c[3])
        : "r"(a0), "r"(a1), "r"(a2), "r"(a3), "r"(b0), "r"(b1));
}
__device__ __forceinline__ unsigned pack_bf2(__nv_bfloat16 a, __nv_bfloat16 b) {
    return (unsigned)__bfloat16_as_ushort(a) |
           ((unsigned)__bfloat16_as_ushort(b) << 16);
}
__device__ __forceinline__ unsigned pack_h2(__half a, __half b) {
    return (unsigned)__half_as_ushort(a) |
           ((unsigned)__half_as_ushort(b) << 16);
}
__device__ __forceinline__ void split_bf(float v, __nv_bfloat16& hi, __nv_bfloat16& lo) {
    hi = __float2bfloat16(v);
    lo = __float2bfloat16(v - __bfloat162float(hi));
}
// split a float2 (two consecutive k-values) into packed hi / lo words
__device__ __forceinline__ void split_pack2(float2 v, unsigned& ph, unsigned& pl) {
    __nv_bfloat16 h0, l0, h1, l1;
    split_bf(v.x, h0, l0);
    split_bf(v.y, h1, l1);
    ph = pack_bf2(h0, h1);
    pl = pack_bf2(l0, l1);
}
__device__ __forceinline__ int cfirst_of(int ut) {
    return (ut < CF_THRESH) ? (ut / 56) : ((ut - UNIT_R) / UNIT_Q);
}

// ---------------- split: Wcat^T -> bf16 hi/lo (W only; h handled in prep) --
// grid 32 x 256: t = col*32 + k-quarter
__global__ __launch_bounds__(256)
void split_kernel(const float* __restrict__ Ws,
                  const float* __restrict__ Wt,
                  const float* __restrict__ Wc) {
    int t  = blockIdx.x * 256 + threadIdx.x;    // 0..8191
    int c  = t >> 5;                            // concat col 0..255
    int k0 = (t & 31) * 4;
    const float* W; int stride, cc;
    if (c < 64)       { W = Ws; stride = 64;  cc = c; }
    else if (c < 128) { W = Wt; stride = 64;  cc = c - 64; }
    else              { W = Wc; stride = 128; cc = c - 128; }
    union { __nv_bfloat16 b[4]; uint2 u; } ph, pl;
#pragma unroll
    for (int j = 0; j < 4; j++)
        split_bf(W[(k0 + j) * stride + cc], ph.b[j], pl.b[j]);
    *(uint2*)(g_Wth + c * IN_F + k0) = ph.u;
    *(uint2*)(g_Wtl + c * IN_F + k0) = pl.u;
}

// ---------------- gemm_prep: C = h @ Wcat (3-term bf16), fp32 h in-kernel --
// grid 256: mtile = bx & 127 (64 rows), ntile = bx >> 7 (128 cols). 128 threads.
__global__ __launch_bounds__(128, 2)
void gemm_prep(const float* __restrict__ h) {
    extern __shared__ __align__(16) unsigned char psmem[];
    unsigned* sBh = (unsigned*)psmem;                    // [128][68 words]
    unsigned* sBl = sBh + 128 * PSTRW;

    const int tid  = threadIdx.x;
    const int warp = tid >> 5;
    const int lane = tid & 31;
    const int lr   = lane >> 2;
    const int qi   = lane & 3;

    const int mtile = blockIdx.x & 127;
    const int ntile = blockIdx.x >> 7;
    const int row0  = mtile * 64 + warp * 16 + lr;
    const int row1  = row0 + 8;

    // B tile fill via cp.async (overlaps the fp32 A loads below)
    {
        const uint4* gWh4 = (const uint4*)g_Wth;
        const uint4* gWl4 = (const uint4*)g_Wtl;
        uint4* sBh4 = (uint4*)sBh;
        uint4* sBl4 = (uint4*)sBl;
#pragma unroll
        for (int i = tid; i < 2048; i += 128) {
            int r = i >> 4, u = i & 15;
            cp16(&sBh4[r * PSTR4 + u], &gWh4[(ntile * 128 + r) * 16 + u]);
            cp16(&sBl4[r * PSTR4 + u], &gWl4[(ntile * 128 + r) * 16 + u]);
        }
        cp_commit();
    }

    // A fragments from fp32 h, split in registers.
    const float* h0p = h + (size_t)row0 * IN_F;
    const float* h1p = h + (size_t)row1 * IN_F;
    unsigned ah[8][4], al[8][4];
#pragma unroll
    for (int kt = 0; kt < 8; kt++) {
        int k = 2 * qi + 16 * kt;
        split_pack2(*(const float2*)&h0p[k],     ah[kt][0], al[kt][0]);
        split_pack2(*(const float2*)&h1p[k],     ah[kt][1], al[kt][1]);
        split_pack2(*(const float2*)&h0p[k + 8], ah[kt][2], al[kt][2]);
        split_pack2(*(const float2*)&h1p[k + 8], ah[kt][3], al[kt][3]);
    }

    float C[16][4];
#pragma unroll
    for (int nt = 0; nt < 16; nt++)
        C[nt][0] = C[nt][1] = C[nt][2] = C[nt][3] = 0.f;

    cp_wait<0>();
    __syncthreads();

#pragma unroll
    for (int kt = 0; kt < 8; kt++) {
#pragma unroll
        for (int g2 = 0; g2 < 4; g2++) {
            unsigned b0[4], b1[4], c0[4], c1[4];
#pragma unroll
            for (int i = 0; i < 4; i++) {
                int nt = 4 * g2 + i;
                int bi = (8 * nt + lr) * PSTRW + qi + 8 * kt;
                b0[i] = sBh[bi]; b1[i] = sBh[bi + 4];
                c0[i] = sBl[bi]; c1[i] = sBl[bi + 4];
            }
#pragma unroll
            for (int i = 0; i < 4; i++)
                mma_bf16(C[4*g2+i], ah[kt][0], ah[kt][1], ah[kt][2], ah[kt][3], b0[i], b1[i]);
#pragma unroll
            for (int i = 0; i < 4; i++)
                mma_bf16(C[4*g2+i], al[kt][0], al[kt][1], al[kt][2], al[kt][3], b0[i], b1[i]);
#pragma unroll
            for (int i = 0; i < 4; i++)
                mma_bf16(C[4*g2+i], ah[kt][0], ah[kt][1], ah[kt][2], ah[kt][3], c0[i], c1[i]);
        }
    }

    if (ntile == 0) {
#pragma unroll
        for (int nt = 0; nt < 16; nt++) {
            __nv_bfloat16 h0, l0, h1, l1, h2, l2, h3, l3;
            split_bf(C[nt][0], h0, l0); split_bf(C[nt][1], h1, l1);
            split_bf(C[nt][2], h2, l2); split_bf(C[nt][3], h3, l3);
            int col = 8 * nt + 2 * qi;
            __nv_bfloat16* dh = (col < 64) ? g_Qh : g_Kh;
            __nv_bfloat16* dl = (col < 64) ? g_Ql : g_Kl;
            int c = col & 63;
            *(unsigned*)&dh[(size_t)row0 * HID + c] = pack_bf2(h0, h1);
            *(unsigned*)&dl[(size_t)row0 * HID + c] = pack_bf2(l0, l1);
            *(unsigned*)&dh[(size_t)row1 * HID + c] = pack_bf2(h2, h3);
            *(unsigned*)&dl[(size_t)row1 * HID + c] = pack_bf2(l2, l3);
        }
    } else {
#pragma unroll
        for (int nt = 0; nt < 16; nt++) {
            int col = 8 * nt + 2 * qi;
            g_Vt[(size_t)col       * N_NODES + row0] = __float2half_rn(C[nt][0]);
            g_Vt[(size_t)(col + 1) * N_NODES + row0] = __float2half_rn(C[nt][1]);
            g_Vt[(size_t)col       * N_NODES + row1] = __float2half_rn(C[nt][2]);
            g_Vt[(size_t)(col + 1) * N_NODES + row1] = __float2half_rn(C[nt][3]);
        }
    }
}

// ---------------- flash attention (persistent, occ 2 — R10 config) ---------
// grid = 296 CTAs; CTA c owns flattened units [start(c), start(c+1)).
__global__ __launch_bounds__(128, 2)
void flash_kernel(const int* __restrict__ adj) {
    extern __shared__ __align__(16) unsigned char dynsmem[];
    uint4* base4 = (uint4*)dynsmem;

    const int tid  = threadIdx.x;
    const int warp = tid >> 5;
    const int lane = tid & 31;
    const int lr   = lane >> 2;
    const int qi   = lane & 3;

    const int c  = blockIdx.x;
    const int u0 = UNIT_Q * c + min(c, UNIT_R);
    const int u1 = u0 + UNIT_Q + (c < UNIT_R ? 1 : 0);

    const int2*  adj2 = (const int2*)adj;
    const uint4* gKh4 = (const uint4*)g_Kh;
    const uint4* gKl4 = (const uint4*)g_Kl;
    const uint4* gV4  = (const uint4*)g_Vt;
    const unsigned* qh32 = (const unsigned*)g_Qh;
    const unsigned* ql32 = (const unsigned*)g_Ql;

    int u = u0;
    while (u < u1) {
        const int t    = u >> 7;           // m-tile
        const int jb0  = u & 127;          // first j-block in this tile
        const int nit  = min(128 - jb0, u1 - u);
        const int slot = c - cfirst_of(t << 7);
        const int jbase = jb0 * BN;

        const int mr   = t * BM + warp * 16;
        const int row0 = mr + lr;
        const int row1 = row0 + 8;

        // Q fragments (hi/lo)
        unsigned qh[4][4], ql[4][4];
#pragma unroll
        for (int kt = 0; kt < 4; kt++) {
            int b0 = row0 * 32 + qi + 8 * kt;
            int b1 = row1 * 32 + qi + 8 * kt;
            qh[kt][0] = qh32[b0];     qh[kt][1] = qh32[b1];
            qh[kt][2] = qh32[b0 + 4]; qh[kt][3] = qh32[b1 + 4];
            ql[kt][0] = ql32[b0];     ql[kt][1] = ql32[b1];
            ql[kt][2] = ql32[b0 + 4]; ql[kt][3] = ql32[b1 + 4];
        }

        float O[16][4];
#pragma unroll
        for (int v = 0; v < 16; v++)
#pragma unroll
            for (int i = 0; i < 4; i++) O[v][i] = 0.f;
        float m0 = -1e30f, m1 = -1e30f, l0 = 0.f, l1 = 0.f;

        // segment prologue: prior segment done before refill
        __syncthreads();
        {
            uint4* bKh = base4;
            uint4* bKl = base4 + 576;
            uint4* bV  = base4 + 1152;
#pragma unroll
            for (int i = tid; i < 512; i += 128) {
                int r = i >> 3, cw = i & 7;
                cp16(&bKh[r * KSTR4 + cw], &gKh4[(jbase + r) * 8 + cw]);
                cp16(&bKl[r * KSTR4 + cw], &gKl4[(jbase + r) * 8 + cw]);
            }
#pragma unroll
            for (int i = tid; i < 1024; i += 128) {
                int cl2 = i >> 3, kw = i & 7;
                cp16(&bV[cl2 * KSTR4 + kw], &gV4[cl2 * 1024 + (jbase >> 3) + kw]);
            }
            cp_commit();
        }

        int b_cur = 0;
        for (int it = 0; it < nit; ++it) {
            const int j0 = jbase + it * BN;

            int2 adjA[8], adjB[8];
#pragma unroll
            for (int nt = 0; nt < 8; nt++) {
                adjA[nt] = __ldcs(&adj2[row0 * 4096 + (j0 >> 1) + 4 * nt + qi]);
                adjB[nt] = __ldcs(&adj2[row1 * 4096 + (j0 >> 1) + 4 * nt + qi]);
            }

            cp_wait<0>();
            __syncthreads();   // single barrier per iter (3-buffer reuse distance 2)

            if (it + 1 < nit) {
                const int jn = j0 + BN;
                const int b_nxt = (b_cur == 2) ? 0 : b_cur + 1;
                uint4* bKh = base4 + b_nxt * BUF_U4;
                uint4* bKl = bKh + 576;
                uint4* bV  = bKh + 1152;
#pragma unroll
                for (int i = tid; i < 512; i += 128) {
                    int r = i >> 3, cw = i & 7;
                    cp16(&bKh[r * KSTR4 + cw], &gKh4[(jn + r) * 8 + cw]);
                    cp16(&bKl[r * KSTR4 + cw], &gKl4[(jn + r) * 8 + cw]);
                }
#pragma unroll
                for (int i = tid; i < 1024; i += 128) {
                    int cl2 = i >> 3, kw = i & 7;
                    cp16(&bV[cl2 * KSTR4 + kw], &gV4[cl2 * 1024 + (jn >> 3) + kw]);
                }
                cp_commit();
            }

            const unsigned* sKh32 = (const unsigned*)(base4 + b_cur * BUF_U4);
            const unsigned* sKl32 = sKh32 + 576 * 4;
            const unsigned* sV32  = sKh32 + 1152 * 4;

            // S = Q K^T (3-term bf16 split, chains interleaved x4)
            float S[8][4];
#pragma unroll
            for (int nt = 0; nt < 8; nt++)
                S[nt][0] = S[nt][1] = S[nt][2] = S[nt][3] = 0.f;

#pragma unroll
            for (int kt = 0; kt < 4; kt++) {
#pragma unroll
                for (int gr = 0; gr < 2; gr++) {
                    unsigned b0[4], b1[4], c0[4], c1[4];
#pragma unroll
                    for (int i = 0; i < 4; i++) {
                        int nt = 4 * gr + i;
                        int bi = (8 * nt + lr) * KSTRW + qi + 8 * kt;
                        b0[i] = sKh32[bi]; b1[i] = sKh32[bi + 4];
                        c0[i] = sKl32[bi]; c1[i] = sKl32[bi + 4];
                    }
#pragma unroll
                    for (int i = 0; i < 4; i++)
                        mma_bf16(S[4*gr+i], qh[kt][0], qh[kt][1], qh[kt][2], qh[kt][3], b0[i], b1[i]);
#pragma unroll
                    for (int i = 0; i < 4; i++)
                        mma_bf16(S[4*gr+i], ql[kt][0], ql[kt][1], ql[kt][2], ql[kt][3], b0[i], b1[i]);
#pragma unroll
                    for (int i = 0; i < 4; i++)
                        mma_bf16(S[4*gr+i], qh[kt][0], qh[kt][1], qh[kt][2], qh[kt][3], c0[i], c1[i]);
                }
            }

            // mask + row max
            float rmax0 = -1e30f, rmax1 = -1e30f;
#pragma unroll
            for (int nt = 0; nt < 8; nt++) {
                if (adjA[nt].x <= 0) S[nt][0] = -1e30f;
                if (adjA[nt].y <= 0) S[nt][1] = -1e30f;
                if (adjB[nt].x <= 0) S[nt][2] = -1e30f;
                if (adjB[nt].y <= 0) S[nt][3] = -1e30f;
                rmax0 = fmaxf(rmax0, fmaxf(S[nt][0], S[nt][1]));
                rmax1 = fmaxf(rmax1, fmaxf(S[nt][2], S[nt][3]));
            }
            rmax0 = fmaxf(rmax0, __shfl_xor_sync(0xffffffffu, rmax0, 1));
            rmax0 = fmaxf(rmax0, __shfl_xor_sync(0xffffffffu, rmax0, 2));
            rmax1 = fmaxf(rmax1, __shfl_xor_sync(0xffffffffu, rmax1, 1));
            rmax1 = fmaxf(rmax1, __shfl_xor_sync(0xffffffffu, rmax1, 2));

            float mn0 = fmaxf(m0, rmax0), mn1 = fmaxf(m1, rmax1);
            float sc0 = __expf(m0 - mn0), sc1 = __expf(m1 - mn1);
            m0 = mn0; m1 = mn1;

            // exp + pack P (fp16)
            float rs0 = 0.f, rs1 = 0.f;
            unsigned ap[4][4];
#pragma unroll
            for (int kt2 = 0; kt2 < 4; kt2++) {
#pragma unroll
                for (int half = 0; half < 2; half++) {
                    int nt = 2 * kt2 + half;
                    float p0 = (S[nt][0] > -1e29f) ? __expf(S[nt][0] - mn0) : 0.f;
                    float p1 = (S[nt][1] > -1e29f) ? __expf(S[nt][1] - mn0) : 0.f;
                    float p2 = (S[nt][2] > -1e29f) ? __expf(S[nt][2] - mn1) : 0.f;
                    float p3 = (S[nt][3] > -1e29f) ? __expf(S[nt][3] - mn1) : 0.f;
                    rs0 += p0 + p1;
                    rs1 += p2 + p3;
                    ap[kt2][2 * half + 0] = pack_h2(__float2half_rn(p0), __float2half_rn(p1));
                    ap[kt2][2 * half + 1] = pack_h2(__float2half_rn(p2), __float2half_rn(p3));
                }
            }

            rs0 += __shfl_xor_sync(0xffffffffu, rs0, 1);
            rs0 += __shfl_xor_sync(0xffffffffu, rs0, 2);
            rs1 += __shfl_xor_sync(0xffffffffu, rs1, 1);
            rs1 += __shfl_xor_sync(0xffffffffu, rs1, 2);
            l0 = l0 * sc0 + rs0;
            l1 = l1 * sc1 + rs1;

            if (!__all_sync(0xffffffffu, (sc0 == 1.f) & (sc1 == 1.f))) {
#pragma unroll
                for (int v = 0; v < 16; v++) {
                    O[v][0] *= sc0; O[v][1] *= sc0;
                    O[v][2] *= sc1; O[v][3] *= sc1;
                }
            }

            // O += P V (single fp16 term, chains interleaved x4)
#pragma unroll
            for (int kt2 = 0; kt2 < 4; kt2++) {
#pragma unroll
                for (int gr = 0; gr < 4; gr++) {
                    unsigned v0[4], v1[4];
#pragma unroll
                    for (int i = 0; i < 4; i++) {
                        int vn = 4 * gr + i;
                        int bi = (8 * vn + lr) * KSTRW + qi + 8 * kt2;
                        v0[i] = sV32[bi]; v1[i] = sV32[bi + 4];
                    }
#pragma unroll
                    for (int i = 0; i < 4; i++)
                        mma_f16(O[4*gr+i], ap[kt2][0], ap[kt2][1], ap[kt2][2], ap[kt2][3], v0[i], v1[i]);
                }
            }

            b_cur = (b_cur == 2) ? 0 : b_cur + 1;
        }

        // store NORMALIZED partials (fp16) + (m, l)
        float inv0 = (l0 > 0.f) ? 1.f / l0 : 0.f;
        float inv1 = (l1 > 0.f) ? 1.f / l1 : 0.f;
        __half* oph = &g_Oph[slot][0][0];
#pragma unroll
        for (int vn = 0; vn < 16; vn++) {
            int col = 8 * vn + 2 * qi;
            *(unsigned*)&oph[row0 * OUT_F + col] =
                pack_h2(__float2half_rn(O[vn][0] * inv0), __float2half_rn(O[vn][1] * inv0));
            *(unsigned*)&oph[row1 * OUT_F + col] =
                pack_h2(__float2half_rn(O[vn][2] * inv1), __float2half_rn(O[vn][3] * inv1));
        }
        if (qi == 0) {
            g_pm[slot][row0] = m0; g_pl[slot][row0] = l0;
            g_pm[slot][row1] = m1; g_pl[slot][row1] = l1;
        }

        u += nit;
    }
}

// ---------------- merge partial slots (unrolled, predicated) ----------------
// grid 512 x 256: block = 8 rows (2 per thread-row-group), thread = 4 cols of 2 rows
// thread handles rows {rowA, rowA+4} to double MLP.
__global__ __launch_bounds__(256)
void merge_kernel(float* __restrict__ out) {
    const int rg  = threadIdx.x >> 5;            // 0..7
    const int rowA = blockIdx.x * 16 + rg;       // rows rowA and rowA+8
    const int rowB = rowA + 8;
    const int cc  = (threadIdx.x & 31) * 4;

    // same m-tile for both rows (16-row block within one 64-row tile)
    const int t  = rowA >> 6;
    const int ut = t << 7;
    const int ns = cfirst_of(ut + 127) - cfirst_of(ut) + 1;   // 2..4

    // batched loads: all slots up front, predicated by ok
    float msA[SLOTS], lsA[SLOTS], msB[SLOTS], lsB[SLOTS];
    uint2 pvA[SLOTS], pvB[SLOTS];
#pragma unroll
    for (int s = 0; s < SLOTS; s++) {
        bool ok = (s < ns);
        msA[s] = ok ? g_pm[s][rowA] : -1e30f;
        lsA[s] = ok ? g_pl[s][rowA] : 0.f;
        msB[s] = ok ? g_pm[s][rowB] : -1e30f;
        lsB[s] = ok ? g_pl[s][rowB] : 0.f;
        pvA[s] = *(const uint2*)&g_Oph[ok ? s : 0][rowA][cc];
        pvB[s] = *(const uint2*)&g_Oph[ok ? s : 0][rowB][cc];
    }

    float MA = fmaxf(fmaxf(msA[0], msA[1]), fmaxf(msA[2], msA[3]));
    float MB = fmaxf(fmaxf(msB[0], msB[1]), fmaxf(msB[2], msB[3]));

    float a0 = 0.f, a1 = 0.f, a2 = 0.f, a3 = 0.f, dA = 0.f;
    float b0 = 0.f, b1 = 0.f, b2 = 0.f, b3 = 0.f, dB = 0.f;
#pragma unroll
    for (int s = 0; s < SLOTS; s++) {
        float wA = lsA[s] * __expf(msA[s] - MA);
        float wB = lsB[s] * __expf(msB[s] - MB);
        dA += wA; dB += wB;
        __half2 hA01 = *(__half2*)&pvA[s].x;
        __half2 hA23 = *(__half2*)&pvA[s].y;
        __half2 hB01 = *(__half2*)&pvB[s].x;
        __half2 hB23 = *(__half2*)&pvB[s].y;
        a0 += wA * __half2float(__low2half(hA01));
        a1 += wA * __half2float(__high2half(hA01));
        a2 += wA * __half2float(__low2half(hA23));
        a3 += wA * __half2float(__high2half(hA23));
        b0 += wB * __half2float(__low2half(hB01));
        b1 += wB * __half2float(__high2half(hB01));
        b2 += wB * __half2float(__low2half(hB23));
        b3 += wB * __half2float(__high2half(hB23));
    }
    float iA = 1.f / dA;
    float iB = 1.f / dB;
    *(float4*)&out[rowA * OUT_F + cc] = make_float4(a0 * iA, a1 * iA, a2 * iA, a3 * iA);
    *(float4*)&out[rowB * OUT_F + cc] = make_float4(b0 * iB, b1 * iB, b2 * iB, b3 * iB);
}

// ---------------- launch --------------------------------------------------
extern "C" void kernel_launch(void* const* d_in, const int* in_sizes, int n_in,
                              void* d_out, int out_size) {
    const float* h   = (const float*)d_in[0];
    const int*   adj = (const int*)d_in[1];
    const float* Ws  = (const float*)d_in[2];
    const float* Wt  = (const float*)d_in[3];
    const float* Wc  = (const float*)d_in[4];
    float* out = (float*)d_out;

    split_kernel<<<32, 256>>>(Ws, Wt, Wc);

    cudaFuncSetAttribute(gemm_prep,
                         cudaFuncAttributeMaxDynamicSharedMemorySize, PREP_SMEM);
    gemm_prep<<<256, 128, PREP_SMEM>>>(h);

    cudaFuncSetAttribute(flash_kernel,
                         cudaFuncAttributeMaxDynamicSharedMemorySize, FLASH_SMEM);
    flash_kernel<<<N_CTAS, 128, FLASH_SMEM>>>(adj);

    merge_kernel<<<N_NODES / 16, 256>>>(out);
}

// round 17
// speedup vs baseline: 1.0356x; 1.0069x over previous
#include <cuda_runtime.h>
#include <cuda_bf16.h>
#include <cuda_fp16.h>
#include <cstdint>

#define N_NODES 8192
#define IN_F    128
#define HID     64
#define OUT_F   128
#define BM      64
#define BN      64

// persistent schedule: 16384 units = 128 mtiles x 128 jblocks, 296 CTAs
// start(c) = 55c + min(c,104)  (CTAs 0..103 have 56 units, rest 55)
#define N_CTAS  296
#define UNIT_Q  55
#define UNIT_R  104
#define CF_THRESH 5824   // start(104)
#define SLOTS   4

// K/V row stride in flash smem: 64 elems + 8 pad = 72 x 2B = 36 words = 9 uint4.
#define KSTRW 36
#define KSTR4 9
// uint4 per buffer: Kh 576, Kl 576, V 1152 -> 2304 u4 = 36864 B ; 3 buffers
#define BUF_U4 2304
#define FLASH_SMEM (3 * BUF_U4 * 16)   // 110592 B -> 2 CTAs/SM

// gemm_prep smem B row stride: 128 bf16 = 64 words data + 4 pad = 68 words = 17 u4
#define PSTRW 68
#define PSTR4 17
#define PREP_SMEM (2 * 128 * PSTRW * 4)   // Bh + Bl = 69632 B

// ---------------- scratch (static device globals; no allocs allowed) -----
__device__ __align__(16) __nv_bfloat16 g_Qh[N_NODES * HID];
__device__ __align__(16) __nv_bfloat16 g_Ql[N_NODES * HID];
__device__ __align__(16) __nv_bfloat16 g_Kh[N_NODES * HID];
__device__ __align__(16) __nv_bfloat16 g_Kl[N_NODES * HID];
__device__ __align__(16) __half g_Vt[OUT_F * N_NODES];         // V^T fp16 [feat][j]
// partial slots per m-tile: NORMALIZED O in fp16 + (m, l) in fp32
__device__ __align__(16) __half g_Oph[SLOTS][N_NODES][OUT_F];
__device__ float g_pm[SLOTS][N_NODES];
__device__ float g_pl[SLOTS][N_NODES];

// ---------------- helpers --------------------------------------------------
__device__ __forceinline__ void cp16(void* s, const void* g) {
    unsigned sa = (unsigned)__cvta_generic_to_shared(s);
    asm volatile("cp.async.cg.shared.global [%0], [%1], 16;\n" :: "r"(sa), "l"(g));
}
__device__ __forceinline__ void cp_commit() { asm volatile("cp.async.commit_group;\n"); }
template <int N> __device__ __forceinline__ void cp_wait() {
    asm volatile("cp.async.wait_group %0;\n" :: "n"(N));
}
__device__ __forceinline__ void mma_bf16(float c[4],
                                         unsigned a0, unsigned a1, unsigned a2, unsigned a3,
                                         unsigned b0, unsigned b1) {
    asm volatile(
        "mma.sync.aligned.m16n8k16.row.col.f32.bf16.bf16.f32 "
        "{%0,%1,%2,%3}, {%4,%5,%6,%7}, {%8,%9}, {%0,%1,%2,%3};\n"
        : "+f"(c[0]), "+f"(c[1]), "+f"(c[2]), "+f"(c[3])
        : "r"(a0), "r"(a1), "r"(a2), "r"(a3), "r"(b0), "r"(b1));
}
__device__ __forceinline__ void mma_f16(float c[4],
                                        unsigned a0, unsigned a1, unsigned a2, unsigned a3,
                                        unsigned b0, unsigned b1) {
    asm volatile(
        "mma.sync.aligned.m16n8k16.row.col.f32.f16.f16.f32 "
        "{%0,%1,%2,%3}, {%4,%5,%6,%7}, {%8,%9}, {%0,%1,%2,%3};\n"
        : "+f"(c[0]), "+f"(c[1]), "+f"(c[2]), "+f"(c[3])
        : "r"(a0), "r"(a1), "r"(a2), "r"(a3), "r"(b0), "r"(b1));
}
__device__ __forceinline__ unsigned pack_bf2(__nv_bfloat16 a, __nv_bfloat16 b) {
    return (unsigned)__bfloat16_as_ushort(a) |
           ((unsigned)__bfloat16_as_ushort(b) << 16);
}
__device__ __forceinline__ unsigned pack_h2(__half a, __half b) {
    return (unsigned)__half_as_ushort(a) |
           ((unsigned)__half_as_ushort(b) << 16);
}
__device__ __forceinline__ void split_bf(float v, __nv_bfloat16& hi, __nv_bfloat16& lo) {
    hi = __float2bfloat16(v);
    lo = __float2bfloat16(v - __bfloat162float(hi));
}
// split a float2 (two consecutive k-values) into packed hi / lo words
__device__ __forceinline__ void split_pack2(float2 v, unsigned& ph, unsigned& pl) {
    __nv_bfloat16 h0, l0, h1, l1;
    split_bf(v.x, h0, l0);
    split_bf(v.y, h1, l1);
    ph = pack_bf2(h0, h1);
    pl = pack_bf2(l0, l1);
}
__device__ __forceinline__ int cfirst_of(int ut) {
    return (ut < CF_THRESH) ? (ut / 56) : ((ut - UNIT_R) / UNIT_Q);
}

// ---------------- gemm_prep: C = h @ Wcat (3-term bf16), fp32 in-kernel ----
// grid 256: mtile = bx & 127 (64 rows), ntile = bx >> 7 (128 cols). 128 threads.
// W split is done in-kernel: thread = concat col, coalesced per-k fp32 loads
// (W is 128 KB total -> L1/L2-hot), split in regs, conflict-free uint4 STS.
__global__ __launch_bounds__(128, 2)
void gemm_prep(const float* __restrict__ h,
               const float* __restrict__ Ws,
               const float* __restrict__ Wt,
               const float* __restrict__ Wc) {
    extern __shared__ __align__(16) unsigned char psmem[];
    unsigned* sBh = (unsigned*)psmem;                    // [128][68 words]
    unsigned* sBl = sBh + 128 * PSTRW;

    const int tid  = threadIdx.x;
    const int warp = tid >> 5;
    const int lane = tid & 31;
    const int lr   = lane >> 2;
    const int qi   = lane & 3;

    const int mtile = blockIdx.x & 127;
    const int ntile = blockIdx.x >> 7;
    const int row0  = mtile * 64 + warp * 16 + lr;
    const int row1  = row0 + 8;

    // ---- B tile: load fp32 W column, split, store to smem -------------
    {
        const int gcol = ntile * 128 + tid;     // concat col 0..255
        const float* W; int stride, cc;
        if (gcol < 64)       { W = Ws; stride = 64;  cc = gcol; }
        else if (gcol < 128) { W = Wt; stride = 64;  cc = gcol - 64; }
        else                 { W = Wc; stride = 128; cc = gcol - 128; }
        unsigned* dh = &sBh[tid * PSTRW];
        unsigned* dl = &sBl[tid * PSTRW];
#pragma unroll
        for (int j = 0; j < 8; j++) {           // 8 chunks of 16 k-values
            unsigned ph[8], pl[8];
#pragma unroll
            for (int q = 0; q < 8; q++) {
                int k = 16 * j + 2 * q;
                float v0 = __ldg(&W[k * stride + cc]);
                float v1 = __ldg(&W[(k + 1) * stride + cc]);
                split_pack2(make_float2(v0, v1), ph[q], pl[q]);
            }
            *(uint4*)&dh[8 * j]     = make_uint4(ph[0], ph[1], ph[2], ph[3]);
            *(uint4*)&dh[8 * j + 4] = make_uint4(ph[4], ph[5], ph[6], ph[7]);
            *(uint4*)&dl[8 * j]     = make_uint4(pl[0], pl[1], pl[2], pl[3]);
            *(uint4*)&dl[8 * j + 4] = make_uint4(pl[4], pl[5], pl[6], pl[7]);
        }
    }

    // ---- A fragments from fp32 h, split in registers ------------------
    const float* h0p = h + (size_t)row0 * IN_F;
    const float* h1p = h + (size_t)row1 * IN_F;
    unsigned ah[8][4], al[8][4];
#pragma unroll
    for (int kt = 0; kt < 8; kt++) {
        int k = 2 * qi + 16 * kt;
        split_pack2(*(const float2*)&h0p[k],     ah[kt][0], al[kt][0]);
        split_pack2(*(const float2*)&h1p[k],     ah[kt][1], al[kt][1]);
        split_pack2(*(const float2*)&h0p[k + 8], ah[kt][2], al[kt][2]);
        split_pack2(*(const float2*)&h1p[k + 8], ah[kt][3], al[kt][3]);
    }

    float C[16][4];
#pragma unroll
    for (int nt = 0; nt < 16; nt++)
        C[nt][0] = C[nt][1] = C[nt][2] = C[nt][3] = 0.f;

    __syncthreads();

#pragma unroll
    for (int kt = 0; kt < 8; kt++) {
#pragma unroll
        for (int g2 = 0; g2 < 4; g2++) {
            unsigned b0[4], b1[4], c0[4], c1[4];
#pragma unroll
            for (int i = 0; i < 4; i++) {
                int nt = 4 * g2 + i;
                int bi = (8 * nt + lr) * PSTRW + qi + 8 * kt;
                b0[i] = sBh[bi]; b1[i] = sBh[bi + 4];
                c0[i] = sBl[bi]; c1[i] = sBl[bi + 4];
            }
#pragma unroll
            for (int i = 0; i < 4; i++)
                mma_bf16(C[4*g2+i], ah[kt][0], ah[kt][1], ah[kt][2], ah[kt][3], b0[i], b1[i]);
#pragma unroll
            for (int i = 0; i < 4; i++)
                mma_bf16(C[4*g2+i], al[kt][0], al[kt][1], al[kt][2], al[kt][3], b0[i], b1[i]);
#pragma unroll
            for (int i = 0; i < 4; i++)
                mma_bf16(C[4*g2+i], ah[kt][0], ah[kt][1], ah[kt][2], ah[kt][3], c0[i], c1[i]);
        }
    }

    if (ntile == 0) {
#pragma unroll
        for (int nt = 0; nt < 16; nt++) {
            __nv_bfloat16 h0, l0, h1, l1, h2, l2, h3, l3;
            split_bf(C[nt][0], h0, l0); split_bf(C[nt][1], h1, l1);
            split_bf(C[nt][2], h2, l2); split_bf(C[nt][3], h3, l3);
            int col = 8 * nt + 2 * qi;
            __nv_bfloat16* dh = (col < 64) ? g_Qh : g_Kh;
            __nv_bfloat16* dl = (col < 64) ? g_Ql : g_Kl;
            int c = col & 63;
            *(unsigned*)&dh[(size_t)row0 * HID + c] = pack_bf2(h0, h1);
            *(unsigned*)&dl[(size_t)row0 * HID + c] = pack_bf2(l0, l1);
            *(unsigned*)&dh[(size_t)row1 * HID + c] = pack_bf2(h2, h3);
            *(unsigned*)&dl[(size_t)row1 * HID + c] = pack_bf2(l2, l3);
        }
    } else {
#pragma unroll
        for (int nt = 0; nt < 16; nt++) {
            int col = 8 * nt + 2 * qi;
            g_Vt[(size_t)col       * N_NODES + row0] = __float2half_rn(C[nt][0]);
            g_Vt[(size_t)(col + 1) * N_NODES + row0] = __float2half_rn(C[nt][1]);
            g_Vt[(size_t)col       * N_NODES + row1] = __float2half_rn(C[nt][2]);
            g_Vt[(size_t)(col + 1) * N_NODES + row1] = __float2half_rn(C[nt][3]);
        }
    }
}

// ---------------- flash attention (persistent, occ 2 — R10 config) ---------
// grid = 296 CTAs; CTA c owns flattened units [start(c), start(c+1)).
__global__ __launch_bounds__(128, 2)
void flash_kernel(const int* __restrict__ adj) {
    extern __shared__ __align__(16) unsigned char dynsmem[];
    uint4* base4 = (uint4*)dynsmem;

    const int tid  = threadIdx.x;
    const int warp = tid >> 5;
    const int lane = tid & 31;
    const int lr   = lane >> 2;
    const int qi   = lane & 3;

    const int c  = blockIdx.x;
    const int u0 = UNIT_Q * c + min(c, UNIT_R);
    const int u1 = u0 + UNIT_Q + (c < UNIT_R ? 1 : 0);

    const int2*  adj2 = (const int2*)adj;
    const uint4* gKh4 = (const uint4*)g_Kh;
    const uint4* gKl4 = (const uint4*)g_Kl;
    const uint4* gV4  = (const uint4*)g_Vt;
    const unsigned* qh32 = (const unsigned*)g_Qh;
    const unsigned* ql32 = (const unsigned*)g_Ql;

    int u = u0;
    while (u < u1) {
        const int t    = u >> 7;           // m-tile
        const int jb0  = u & 127;          // first j-block in this tile
        const int nit  = min(128 - jb0, u1 - u);
        const int slot = c - cfirst_of(t << 7);
        const int jbase = jb0 * BN;

        const int mr   = t * BM + warp * 16;
        const int row0 = mr + lr;
        const int row1 = row0 + 8;

        // Q fragments (hi/lo)
        unsigned qh[4][4], ql[4][4];
#pragma unroll
        for (int kt = 0; kt < 4; kt++) {
            int b0 = row0 * 32 + qi + 8 * kt;
            int b1 = row1 * 32 + qi + 8 * kt;
            qh[kt][0] = qh32[b0];     qh[kt][1] = qh32[b1];
            qh[kt][2] = qh32[b0 + 4]; qh[kt][3] = qh32[b1 + 4];
            ql[kt][0] = ql32[b0];     ql[kt][1] = ql32[b1];
            ql[kt][2] = ql32[b0 + 4]; ql[kt][3] = ql32[b1 + 4];
        }

        float O[16][4];
#pragma unroll
        for (int v = 0; v < 16; v++)
#pragma unroll
            for (int i = 0; i < 4; i++) O[v][i] = 0.f;
        float m0 = -1e30f, m1 = -1e30f, l0 = 0.f, l1 = 0.f;

        // segment prologue: prior segment done before refill
        __syncthreads();
        {
            uint4* bKh = base4;
            uint4* bKl = base4 + 576;
            uint4* bV  = base4 + 1152;
#pragma unroll
            for (int i = tid; i < 512; i += 128) {
                int r = i >> 3, cw = i & 7;
                cp16(&bKh[r * KSTR4 + cw], &gKh4[(jbase + r) * 8 + cw]);
                cp16(&bKl[r * KSTR4 + cw], &gKl4[(jbase + r) * 8 + cw]);
            }
#pragma unroll
            for (int i = tid; i < 1024; i += 128) {
                int cl2 = i >> 3, kw = i & 7;
                cp16(&bV[cl2 * KSTR4 + kw], &gV4[cl2 * 1024 + (jbase >> 3) + kw]);
            }
            cp_commit();
        }

        int b_cur = 0;
        for (int it = 0; it < nit; ++it) {
            const int j0 = jbase + it * BN;

            int2 adjA[8], adjB[8];
#pragma unroll
            for (int nt = 0; nt < 8; nt++) {
                adjA[nt] = __ldcs(&adj2[row0 * 4096 + (j0 >> 1) + 4 * nt + qi]);
                adjB[nt] = __ldcs(&adj2[row1 * 4096 + (j0 >> 1) + 4 * nt + qi]);
            }

            cp_wait<0>();
            __syncthreads();   // single barrier per iter (3-buffer reuse distance 2)

            if (it + 1 < nit) {
                const int jn = j0 + BN;
                const int b_nxt = (b_cur == 2) ? 0 : b_cur + 1;
                uint4* bKh = base4 + b_nxt * BUF_U4;
                uint4* bKl = bKh + 576;
                uint4* bV  = bKh + 1152;
#pragma unroll
                for (int i = tid; i < 512; i += 128) {
                    int r = i >> 3, cw = i & 7;
                    cp16(&bKh[r * KSTR4 + cw], &gKh4[(jn + r) * 8 + cw]);
                    cp16(&bKl[r * KSTR4 + cw], &gKl4[(jn + r) * 8 + cw]);
                }
#pragma unroll
                for (int i = tid; i < 1024; i += 128) {
                    int cl2 = i >> 3, kw = i & 7;
                    cp16(&bV[cl2 * KSTR4 + kw], &gV4[cl2 * 1024 + (jn >> 3) + kw]);
                }
                cp_commit();
            }

            const unsigned* sKh32 = (const unsigned*)(base4 + b_cur * BUF_U4);
            const unsigned* sKl32 = sKh32 + 576 * 4;
            const unsigned* sV32  = sKh32 + 1152 * 4;

            // S = Q K^T (3-term bf16 split, chains interleaved x4)
            float S[8][4];
#pragma unroll
            for (int nt = 0; nt < 8; nt++)
                S[nt][0] = S[nt][1] = S[nt][2] = S[nt][3] = 0.f;

#pragma unroll
            for (int kt = 0; kt < 4; kt++) {
#pragma unroll
                for (int gr = 0; gr < 2; gr++) {
                    unsigned b0[4], b1[4], c0[4], c1[4];
#pragma unroll
                    for (int i = 0; i < 4; i++) {
                        int nt = 4 * gr + i;
                        int bi = (8 * nt + lr) * KSTRW + qi + 8 * kt;
                        b0[i] = sKh32[bi]; b1[i] = sKh32[bi + 4];
                        c0[i] = sKl32[bi]; c1[i] = sKl32[bi + 4];
                    }
#pragma unroll
                    for (int i = 0; i < 4; i++)
                        mma_bf16(S[4*gr+i], qh[kt][0], qh[kt][1], qh[kt][2], qh[kt][3], b0[i], b1[i]);
#pragma unroll
                    for (int i = 0; i < 4; i++)
                        mma_bf16(S[4*gr+i], ql[kt][0], ql[kt][1], ql[kt][2], ql[kt][3], b0[i], b1[i]);
#pragma unroll
                    for (int i = 0; i < 4; i++)
                        mma_bf16(S[4*gr+i], qh[kt][0], qh[kt][1], qh[kt][2], qh[kt][3], c0[i], c1[i]);
                }
            }

            // mask + row max
            float rmax0 = -1e30f, rmax1 = -1e30f;
#pragma unroll
            for (int nt = 0; nt < 8; nt++) {
                if (adjA[nt].x <= 0) S[nt][0] = -1e30f;
                if (adjA[nt].y <= 0) S[nt][1] = -1e30f;
                if (adjB[nt].x <= 0) S[nt][2] = -1e30f;
                if (adjB[nt].y <= 0) S[nt][3] = -1e30f;
                rmax0 = fmaxf(rmax0, fmaxf(S[nt][0], S[nt][1]));
                rmax1 = fmaxf(rmax1, fmaxf(S[nt][2], S[nt][3]));
            }
            rmax0 = fmaxf(rmax0, __shfl_xor_sync(0xffffffffu, rmax0, 1));
            rmax0 = fmaxf(rmax0, __shfl_xor_sync(0xffffffffu, rmax0, 2));
            rmax1 = fmaxf(rmax1, __shfl_xor_sync(0xffffffffu, rmax1, 1));
            rmax1 = fmaxf(rmax1, __shfl_xor_sync(0xffffffffu, rmax1, 2));

            float mn0 = fmaxf(m0, rmax0), mn1 = fmaxf(m1, rmax1);
            float sc0 = __expf(m0 - mn0), sc1 = __expf(m1 - mn1);
            m0 = mn0; m1 = mn1;

            // exp + pack P (fp16)
            float rs0 = 0.f, rs1 = 0.f;
            unsigned ap[4][4];
#pragma unroll
            for (int kt2 = 0; kt2 < 4; kt2++) {
#pragma unroll
                for (int half = 0; half < 2; half++) {
                    int nt = 2 * kt2 + half;
                    float p0 = (S[nt][0] > -1e29f) ? __expf(S[nt][0] - mn0) : 0.f;
                    float p1 = (S[nt][1] > -1e29f) ? __expf(S[nt][1] - mn0) : 0.f;
                    float p2 = (S[nt][2] > -1e29f) ? __expf(S[nt][2] - mn1) : 0.f;
                    float p3 = (S[nt][3] > -1e29f) ? __expf(S[nt][3] - mn1) : 0.f;
                    rs0 += p0 + p1;
                    rs1 += p2 + p3;
                    ap[kt2][2 * half + 0] = pack_h2(__float2half_rn(p0), __float2half_rn(p1));
                    ap[kt2][2 * half + 1] = pack_h2(__float2half_rn(p2), __float2half_rn(p3));
                }
            }

            rs0 += __shfl_xor_sync(0xffffffffu, rs0, 1);
            rs0 += __shfl_xor_sync(0xffffffffu, rs0, 2);
            rs1 += __shfl_xor_sync(0xffffffffu, rs1, 1);
            rs1 += __shfl_xor_sync(0xffffffffu, rs1, 2);
            l0 = l0 * sc0 + rs0;
            l1 = l1 * sc1 + rs1;

            if (!__all_sync(0xffffffffu, (sc0 == 1.f) & (sc1 == 1.f))) {
#pragma unroll
                for (int v = 0; v < 16; v++) {
                    O[v][0] *= sc0; O[v][1] *= sc0;
                    O[v][2] *= sc1; O[v][3] *= sc1;
                }
            }

            // O += P V (single fp16 term, chains interleaved x4)
#pragma unroll
            for (int kt2 = 0; kt2 < 4; kt2++) {
#pragma unroll
                for (int gr = 0; gr < 4; gr++) {
                    unsigned v0[4], v1[4];
#pragma unroll
                    for (int i = 0; i < 4; i++) {
                        int vn = 4 * gr + i;
                        int bi = (8 * vn + lr) * KSTRW + qi + 8 * kt2;
                        v0[i] = sV32[bi]; v1[i] = sV32[bi + 4];
                    }
#pragma unroll
                    for (int i = 0; i < 4; i++)
                        mma_f16(O[4*gr+i], ap[kt2][0], ap[kt2][1], ap[kt2][2], ap[kt2][3], v0[i], v1[i]);
                }
            }

            b_cur = (b_cur == 2) ? 0 : b_cur + 1;
        }

        // store NORMALIZED partials (fp16) + (m, l)
        float inv0 = (l0 > 0.f) ? 1.f / l0 : 0.f;
        float inv1 = (l1 > 0.f) ? 1.f / l1 : 0.f;
        __half* oph = &g_Oph[slot][0][0];
#pragma unroll
        for (int vn = 0; vn < 16; vn++) {
            int col = 8 * vn + 2 * qi;
            *(unsigned*)&oph[row0 * OUT_F + col] =
                pack_h2(__float2half_rn(O[vn][0] * inv0), __float2half_rn(O[vn][1] * inv0));
            *(unsigned*)&oph[row1 * OUT_F + col] =
                pack_h2(__float2half_rn(O[vn][2] * inv1), __float2half_rn(O[vn][3] * inv1));
        }
        if (qi == 0) {
            g_pm[slot][row0] = m0; g_pl[slot][row0] = l0;
            g_pm[slot][row1] = m1; g_pl[slot][row1] = l1;
        }

        u += nit;
    }
}

// ---------------- merge partial slots (unrolled, predicated, uint4) --------
// grid 512 x 256: 16 threads per row (8 cols each), 16 rows per block.
__global__ __launch_bounds__(256)
void merge_kernel(float* __restrict__ out) {
    const int row = blockIdx.x * 16 + (threadIdx.x >> 4);
    const int cc  = (threadIdx.x & 15) * 8;

    const int t  = row >> 6;
    const int ut = t << 7;
    const int ns = cfirst_of(ut + 127) - cfirst_of(ut) + 1;   // 2..4

    // batched loads: all 4 slots up front, predicated
    float ms[SLOTS], ls[SLOTS];
    uint4 pv[SLOTS];
#pragma unroll
    for (int s = 0; s < SLOTS; s++) {
        bool ok = (s < ns);
        ms[s] = ok ? g_pm[s][row] : -1e30f;
        ls[s] = ok ? g_pl[s][row] : 0.f;
        pv[s] = *(const uint4*)&g_Oph[ok ? s : 0][row][cc];
    }

    float M = fmaxf(fmaxf(ms[0], ms[1]), fmaxf(ms[2], ms[3]));

    float acc[8] = {0.f, 0.f, 0.f, 0.f, 0.f, 0.f, 0.f, 0.f};
    float den = 0.f;
#pragma unroll
    for (int s = 0; s < SLOTS; s++) {
        float w = ls[s] * __expf(ms[s] - M);
        den += w;
        __half2 h01 = *(__half2*)&pv[s].x;
        __half2 h23 = *(__half2*)&pv[s].y;
        __half2 h45 = *(__half2*)&pv[s].z;
        __half2 h67 = *(__half2*)&pv[s].w;
        acc[0] += w * __half2float(__low2half(h01));
        acc[1] += w * __half2float(__high2half(h01));
        acc[2] += w * __half2float(__low2half(h23));
        acc[3] += w * __half2float(__high2half(h23));
        acc[4] += w * __half2float(__low2half(h45));
        acc[5] += w * __half2float(__high2half(h45));
        acc[6] += w * __half2float(__low2half(h67));
        acc[7] += w * __half2float(__high2half(h67));
    }
    float inv = 1.f / den;
    *(float4*)&out[row * OUT_F + cc] =
        make_float4(acc[0] * inv, acc[1] * inv, acc[2] * inv, acc[3] * inv);
    *(float4*)&out[row * OUT_F + cc + 4] =
        make_float4(acc[4] * inv, acc[5] * inv, acc[6] * inv, acc[7] * inv);
}

// ---------------- launch --------------------------------------------------
extern "C" void kernel_launch(void* const* d_in, const int* in_sizes, int n_in,
                              void* d_out, int out_size) {
    const float* h   = (const float*)d_in[0];
    const int*   adj = (const int*)d_in[1];
    const float* Ws  = (const float*)d_in[2];
    const float* Wt  = (const float*)d_in[3];
    const float* Wc  = (const float*)d_in[4];
    float* out = (float*)d_out;

    cudaFuncSetAttribute(gemm_prep,
                         cudaFuncAttributeMaxDynamicSharedMemorySize, PREP_SMEM);
    gemm_prep<<<256, 128, PREP_SMEM>>>(h, Ws, Wt, Wc);

    cudaFuncSetAttribute(flash_kernel,
                         cudaFuncAttributeMaxDynamicSharedMemorySize, FLASH_SMEM);
    flash_kernel<<<N_CTAS, 128, FLASH_SMEM>>>(adj);

    merge_kernel<<<N_NODES / 16, 256>>>(out);
}